// round 1
// baseline (speedup 1.0000x reference)
#include <cuda_runtime.h>
#include <math.h>

#define NN 10000
#define EE 160000
#define HH 512
#define EDD 16
#define LNEPS 1e-5f
#define EDGE_SCALE 0.1f

// ---------------- scratch (no allocations allowed) ----------------
__device__ float g_T[(size_t)EE * HH];    // gelu(zm @ msg_w1 + b1)   : E x 512
__device__ float g_agg[(size_t)NN * HH];  // segment-sum of messages  : N x 512
__device__ float g_U[(size_t)NN * HH];    // gelu(zu @ upd_w1 + b1)   : N x 512
__device__ float g_h2[(size_t)NN * HH];   // U @ upd_w2 + b2          : N x 512

__device__ __forceinline__ float gelu_exact(float x) {
    return 0.5f * x * (1.0f + erff(x * 0.70710678118654752440f));
}

// ---------------- kernel 1: zero the aggregation buffer ----------------
__global__ void zero_kernel(float* __restrict__ p, int n) {
    int i = blockIdx.x * blockDim.x + threadIdx.x;
    if (i < n) p[i] = 0.0f;
}

// ---------------- kernel 2: edge update (gate + edge MLP + edge LN) ----------------
// One warp per edge. z = [h[src](512) | h[dst](512) | edge_attr(16)]  (1040)
// 17 dot products per edge: 16 cols of em_w1 + 1 col eg_w.
__global__ __launch_bounds__(256) void edge_update_kernel(
    const float* __restrict__ h,
    const float* __restrict__ edge_attr,
    const float* __restrict__ em_w1, const float* __restrict__ em_b1,
    const float* __restrict__ em_w2, const float* __restrict__ em_b2,
    const float* __restrict__ eg_w,  const float* __restrict__ eg_b,
    const float* __restrict__ en_g,  const float* __restrict__ en_b,
    const int* __restrict__ src, const int* __restrict__ dst,
    float* __restrict__ e_new)
{
    int warp = (blockIdx.x * blockDim.x + threadIdx.x) >> 5;
    int lane = threadIdx.x & 31;
    if (warp >= EE) return;
    int e = warp;
    const float* hs = h + (size_t)src[e] * HH;
    const float* hd = h + (size_t)dst[e] * HH;
    const float* ea = edge_attr + (size_t)e * EDD;

    float acc[17];
#pragma unroll
    for (int j = 0; j < 17; j++) acc[j] = 0.0f;

    for (int i = lane; i < 2 * HH + EDD; i += 32) {
        float z = (i < HH) ? hs[i] : ((i < 2 * HH) ? hd[i - HH] : ea[i - 2 * HH]);
        const float4* wr = reinterpret_cast<const float4*>(em_w1 + (size_t)i * 16);
        float4 w0 = wr[0], w1 = wr[1], w2 = wr[2], w3 = wr[3];
        acc[0]  += z * w0.x; acc[1]  += z * w0.y; acc[2]  += z * w0.z; acc[3]  += z * w0.w;
        acc[4]  += z * w1.x; acc[5]  += z * w1.y; acc[6]  += z * w1.z; acc[7]  += z * w1.w;
        acc[8]  += z * w2.x; acc[9]  += z * w2.y; acc[10] += z * w2.z; acc[11] += z * w2.w;
        acc[12] += z * w3.x; acc[13] += z * w3.y; acc[14] += z * w3.z; acc[15] += z * w3.w;
        acc[16] += z * eg_w[i];
    }
#pragma unroll
    for (int j = 0; j < 17; j++) {
#pragma unroll
        for (int o = 16; o > 0; o >>= 1)
            acc[j] += __shfl_xor_sync(0xffffffffu, acc[j], o);
    }

    float gate = 1.0f / (1.0f + expf(-(acc[16] + eg_b[0])));

    // lanes 0..15 each own one ED dim
    float gv = 0.0f;
    if (lane < 16) gv = gelu_exact(acc[lane] + em_b1[lane]);

    float delta = (lane < 16) ? em_b2[lane] : 0.0f;
#pragma unroll
    for (int k = 0; k < 16; k++) {
        float gk = __shfl_sync(0xffffffffu, gv, k);
        if (lane < 16) delta += gk * em_w2[k * 16 + lane];
    }

    float x = 0.0f;
    if (lane < 16) x = ea[lane] + EDGE_SCALE * gate * delta;

    // LayerNorm over 16 lanes (offsets <= 8 stay within the 16-lane half)
    float s = x;
#pragma unroll
    for (int o = 8; o > 0; o >>= 1) s += __shfl_xor_sync(0xffffffffu, s, o);
    float mu = s * (1.0f / 16.0f);
    float d = x - mu;
    float v = d * d;
#pragma unroll
    for (int o = 8; o > 0; o >>= 1) v += __shfl_xor_sync(0xffffffffu, v, o);
    float r = rsqrtf(v * (1.0f / 16.0f) + LNEPS);
    if (lane < 16)
        e_new[(size_t)e * EDD + lane] = d * r * en_g[lane] + en_b[lane];
}

// ---------------- generic SGEMM: C[M x 512] = epi(A @ W + bias) ----------------
// A[row][k] = k < K1 ? A1[(rowmap? rowmap[row]:row)][k] : A2[row][k-K1]
// EPI: 0 = plain store, 1 = gelu store, 2 = atomicAdd into C[scatter[row]]
template <int EPI>
__global__ __launch_bounds__(256) void sgemm_kernel(
    const float* __restrict__ A1, int lda1,
    const float* __restrict__ A2, int lda2, int K1,
    const int* __restrict__ rowmap,
    const float* __restrict__ W,       // K x 512 row-major
    const float* __restrict__ bias,    // 512
    float* __restrict__ C,             // (M or N_nodes) x 512
    const int* __restrict__ scatter,
    int M, int K)
{
    constexpr int BM = 128, BN = 128, BK = 8;
    __shared__ __align__(16) float As[BK][BM];
    __shared__ __align__(16) float Bs[BK][BN];

    int tid = threadIdx.x;
    int m0 = blockIdx.y * BM;
    int n0 = blockIdx.x * BN;

    // A-tile loader mapping: 2 threads per row, 4 consecutive k each
    int ar  = tid >> 1;
    int ak0 = (tid & 1) * 4;
    int grow_a = m0 + ar;
    const float* a1row = A1;
    const float* a2row = A2;
    bool rowok = (grow_a < M);
    if (rowok) {
        int r1 = rowmap ? rowmap[grow_a] : grow_a;
        a1row = A1 + (size_t)r1 * lda1;
        if (A2) a2row = A2 + (size_t)grow_a * lda2;
    }

    // B-tile loader mapping: float4 along columns
    int bk = tid >> 5;
    int bn = (tid & 31) * 4;

    int tx = tid & 15, ty = tid >> 4;

    float acc[8][8];
#pragma unroll
    for (int i = 0; i < 8; i++)
#pragma unroll
        for (int j = 0; j < 8; j++) acc[i][j] = 0.0f;

    for (int k0 = 0; k0 < K; k0 += BK) {
#pragma unroll
        for (int i = 0; i < 4; i++) {
            int k = k0 + ak0 + i;
            float v = 0.0f;
            if (rowok) v = (k < K1) ? a1row[k] : a2row[k - K1];
            As[ak0 + i][ar] = v;
        }
        {
            float4 wv = *reinterpret_cast<const float4*>(W + (size_t)(k0 + bk) * 512 + n0 + bn);
            *reinterpret_cast<float4*>(&Bs[bk][bn]) = wv;
        }
        __syncthreads();
#pragma unroll
        for (int kk = 0; kk < BK; kk++) {
            float a[8], b[8];
#pragma unroll
            for (int i = 0; i < 8; i++) a[i] = As[kk][ty * 8 + i];
#pragma unroll
            for (int j = 0; j < 8; j++) b[j] = Bs[kk][tx * 8 + j];
#pragma unroll
            for (int i = 0; i < 8; i++)
#pragma unroll
                for (int j = 0; j < 8; j++) acc[i][j] += a[i] * b[j];
        }
        __syncthreads();
    }

#pragma unroll
    for (int i = 0; i < 8; i++) {
        int gr = m0 + ty * 8 + i;
        if (gr >= M) continue;
        int outrow = (EPI == 2) ? scatter[gr] : gr;
#pragma unroll
        for (int j = 0; j < 8; j++) {
            int gc = n0 + tx * 8 + j;
            float v = acc[i][j] + bias[gc];
            if (EPI == 1) v = gelu_exact(v);
            if (EPI == 2) atomicAdd(&C[(size_t)outrow * 512 + gc], v);
            else          C[(size_t)outrow * 512 + gc] = v;
        }
    }
}

// ---------------- kernel: residual + LayerNorm over 512 ----------------
__global__ __launch_bounds__(128) void node_out_kernel(
    const float* __restrict__ h, const float* __restrict__ h2,
    const float* __restrict__ g, const float* __restrict__ b,
    float* __restrict__ out)
{
    int n = blockIdx.x;
    int t = threadIdx.x;  // 128 threads x 4 elems
    const float* hr  = h  + (size_t)n * HH;
    const float* h2r = h2 + (size_t)n * HH;

    float x[4];
    float s = 0.0f;
#pragma unroll
    for (int i = 0; i < 4; i++) {
        int c = t + 128 * i;
        x[i] = hr[c] + h2r[c];
        s += x[i];
    }
    __shared__ float red[4];
#pragma unroll
    for (int o = 16; o > 0; o >>= 1) s += __shfl_xor_sync(0xffffffffu, s, o);
    int warp = t >> 5, lane = t & 31;
    if (lane == 0) red[warp] = s;
    __syncthreads();
    float mu = (red[0] + red[1] + red[2] + red[3]) * (1.0f / 512.0f);

    float v = 0.0f;
#pragma unroll
    for (int i = 0; i < 4; i++) { float d = x[i] - mu; v += d * d; }
#pragma unroll
    for (int o = 16; o > 0; o >>= 1) v += __shfl_xor_sync(0xffffffffu, v, o);
    __syncthreads();
    if (lane == 0) red[warp] = v;
    __syncthreads();
    float var = (red[0] + red[1] + red[2] + red[3]) * (1.0f / 512.0f);
    float r = rsqrtf(var + LNEPS);

#pragma unroll
    for (int i = 0; i < 4; i++) {
        int c = t + 128 * i;
        out[(size_t)n * HH + c] = (x[i] - mu) * r * g[c] + b[c];
    }
}

// ---------------- launch ----------------
extern "C" void kernel_launch(void* const* d_in, const int* in_sizes, int n_in,
                              void* d_out, int out_size)
{
    const float* h       = (const float*)d_in[0];
    const float* edge_a  = (const float*)d_in[1];
    const float* msg_w1  = (const float*)d_in[2];
    const float* msg_b1  = (const float*)d_in[3];
    const float* msg_w2  = (const float*)d_in[4];
    const float* msg_b2  = (const float*)d_in[5];
    const float* upd_w1  = (const float*)d_in[6];
    const float* upd_b1  = (const float*)d_in[7];
    const float* upd_w2  = (const float*)d_in[8];
    const float* upd_b2  = (const float*)d_in[9];
    const float* norm_g  = (const float*)d_in[10];
    const float* norm_b  = (const float*)d_in[11];
    const float* em_w1   = (const float*)d_in[12];
    const float* em_b1   = (const float*)d_in[13];
    const float* em_w2   = (const float*)d_in[14];
    const float* em_b2   = (const float*)d_in[15];
    const float* eg_w    = (const float*)d_in[16];
    const float* eg_b    = (const float*)d_in[17];
    const float* en_g    = (const float*)d_in[18];
    const float* en_b    = (const float*)d_in[19];
    const int*   eindex  = (const int*)d_in[20];
    const int*   src = eindex;
    const int*   dst = eindex + EE;

    float* h_out = (float*)d_out;                       // N*512
    float* e_new = (float*)d_out + (size_t)NN * HH;     // E*16

    float *T, *agg, *U, *h2;
    cudaGetSymbolAddress((void**)&T,   g_T);
    cudaGetSymbolAddress((void**)&agg, g_agg);
    cudaGetSymbolAddress((void**)&U,   g_U);
    cudaGetSymbolAddress((void**)&h2,  g_h2);

    // 1) zero aggregation buffer
    zero_kernel<<<(NN * HH + 255) / 256, 256>>>(agg, NN * HH);

    // 2) edge update -> e_new (written straight into d_out)
    edge_update_kernel<<<EE / 8, 256>>>(h, edge_a, em_w1, em_b1, em_w2, em_b2,
                                        eg_w, eg_b, en_g, en_b, src, dst, e_new);

    // 3) T = gelu([h[src] | e_new] @ msg_w1 + b1)   (E x 528 x 512)
    sgemm_kernel<1><<<dim3(4, (EE + 127) / 128), 256>>>(
        h, HH, e_new, EDD, HH, src, msg_w1, msg_b1, T, nullptr, EE, HH + EDD);

    // 4) agg[dst] += T @ msg_w2 + b2                (E x 512 x 512, atomic scatter)
    sgemm_kernel<2><<<dim3(4, (EE + 127) / 128), 256>>>(
        T, HH, nullptr, 0, HH, nullptr, msg_w2, msg_b2, agg, dst, EE, HH);

    // 5) U = gelu([h | agg] @ upd_w1 + b1)          (N x 1024 x 512)
    sgemm_kernel<1><<<dim3(4, (NN + 127) / 128), 256>>>(
        h, HH, agg, HH, HH, nullptr, upd_w1, upd_b1, U, nullptr, NN, 2 * HH);

    // 6) h2 = U @ upd_w2 + b2                       (N x 512 x 512)
    sgemm_kernel<0><<<dim3(4, (NN + 127) / 128), 256>>>(
        U, HH, nullptr, 0, HH, nullptr, upd_w2, upd_b2, h2, nullptr, NN, HH);

    // 7) h_out = LN(h + h2)
    node_out_kernel<<<NN, 128>>>(h, h2, norm_g, norm_b, h_out);
}

// round 5
// speedup vs baseline: 1.4480x; 1.4480x over previous
#include <cuda_runtime.h>
#include <cuda_bf16.h>
#include <math.h>
#include <stdint.h>

#define NN 10000
#define EE 160000
#define HH 512
#define EDD 16
#define LNEPS 1e-5f
#define EDGE_SCALE 0.1f

// ---------------- scratch (no allocations allowed) ----------------
__device__ __nv_bfloat16 g_Thi[(size_t)EE * HH];
__device__ __nv_bfloat16 g_Tlo[(size_t)EE * HH];
__device__ float         g_agg[(size_t)NN * HH];
__device__ __nv_bfloat16 g_Uhi[(size_t)NN * HH];
__device__ __nv_bfloat16 g_Ulo[(size_t)NN * HH];
__device__ float         g_h2[(size_t)NN * HH];
// transposed + split weights: [512][Kp] bf16 (n-major, k contiguous)
__device__ __nv_bfloat16 g_w1hi[512 * 576],  g_w1lo[512 * 576];   // msg_w1 (K=528,Kp=576)
__device__ __nv_bfloat16 g_w2hi[512 * 512],  g_w2lo[512 * 512];   // msg_w2
__device__ __nv_bfloat16 g_u1hi[512 * 1024], g_u1lo[512 * 1024];  // upd_w1
__device__ __nv_bfloat16 g_u2hi[512 * 512],  g_u2lo[512 * 512];   // upd_w2

__device__ __forceinline__ float gelu_exact(float x) {
    return 0.5f * x * (1.0f + erff(x * 0.70710678118654752440f));
}

__device__ __forceinline__ uint32_t smem_u32(const void* p) {
    uint32_t a;
    asm("{ .reg .u64 t; cvta.to.shared.u64 t, %1; cvt.u32.u64 %0, t; }" : "=r"(a) : "l"(p));
    return a;
}

// swizzle: XOR bits[4:5] with bits[7:8] -> conflict-free 16B ldmatrix/STS on 64B rows
__device__ __host__ __forceinline__ uint32_t sw64(uint32_t x) {
    return x ^ (((x >> 7) & 3u) << 4);
}

__device__ __forceinline__ uint32_t pack_bf16(float a, float b) {
    __nv_bfloat162 p = __floats2bfloat162_rn(a, b);
    return *reinterpret_cast<uint32_t*>(&p);
}

#define LDMATRIX_X4(r0, r1, r2, r3, addr) \
    asm volatile("ldmatrix.sync.aligned.m8n8.x4.shared.b16 {%0,%1,%2,%3}, [%4];" \
                 : "=r"(r0), "=r"(r1), "=r"(r2), "=r"(r3) : "r"(addr))
#define LDMATRIX_X2(r0, r1, addr) \
    asm volatile("ldmatrix.sync.aligned.m8n8.x2.shared.b16 {%0,%1}, [%2];" \
                 : "=r"(r0), "=r"(r1) : "r"(addr))

__device__ __forceinline__ void mma_bf16(float& d0, float& d1, float& d2, float& d3,
                                         uint32_t a0, uint32_t a1, uint32_t a2, uint32_t a3,
                                         uint32_t b0, uint32_t b1) {
    asm volatile(
        "mma.sync.aligned.m16n8k16.row.col.f32.bf16.bf16.f32 "
        "{%0,%1,%2,%3}, {%4,%5,%6,%7}, {%8,%9}, {%0,%1,%2,%3};"
        : "+f"(d0), "+f"(d1), "+f"(d2), "+f"(d3)
        : "r"(a0), "r"(a1), "r"(a2), "r"(a3), "r"(b0), "r"(b1));
}

// ---------------- weight transpose + hi/lo split ----------------
__global__ void wsplit_kernel(const float* __restrict__ W, int K, int Kp,
                              __nv_bfloat16* __restrict__ ohi,
                              __nv_bfloat16* __restrict__ olo) {
    __shared__ float t[32][33];
    int kb = blockIdx.x * 32, nb = blockIdx.y * 32;
    int tx = threadIdx.x, ty = threadIdx.y;  // 32 x 8
#pragma unroll
    for (int r = 0; r < 4; r++) {
        int k = kb + ty + r * 8;
        t[ty + r * 8][tx] = (k < K) ? W[(size_t)k * 512 + nb + tx] : 0.0f;
    }
    __syncthreads();
#pragma unroll
    for (int r = 0; r < 4; r++) {
        int n = nb + ty + r * 8;
        int k = kb + tx;
        float v = t[tx][ty + r * 8];
        __nv_bfloat16 h = __float2bfloat16_rn(v);
        ohi[(size_t)n * Kp + k] = h;
        olo[(size_t)n * Kp + k] = __float2bfloat16_rn(v - __bfloat162float(h));
    }
}

// ---------------- zero ----------------
__global__ void zero_kernel(float4* __restrict__ p, int n4) {
    int i = blockIdx.x * blockDim.x + threadIdx.x;
    if (i < n4) p[i] = make_float4(0.f, 0.f, 0.f, 0.f);
}

// ---------------- HMMA GEMM ----------------
// C[M x 512], CTA tile 128(m) x 128(n), K chunked by 32, 3-pass bf16 hi/lo.
// AMODE 0: A from fp32 (A1 rowmapped | A2 concat at K1), split in-kernel.
// AMODE 1: A from bf16 hi/lo [M][512].
// EPI 0: fp32 store (+bias); EPI 1: gelu -> bf16 hi/lo; EPI 2: red.add scatter (+bias).
template <int AMODE, int EPI>
__global__ __launch_bounds__(256) void mma_gemm(
    const float* __restrict__ A1, const float* __restrict__ A2,
    int lda1, int lda2, int K1, int K,
    const int* __restrict__ rowmap,
    const __nv_bfloat16* __restrict__ a_hi, const __nv_bfloat16* __restrict__ a_lo,
    const __nv_bfloat16* __restrict__ b_hi, const __nv_bfloat16* __restrict__ b_lo, int Kp,
    const float* __restrict__ bias,
    float* __restrict__ outf,
    __nv_bfloat16* __restrict__ out_hi, __nv_bfloat16* __restrict__ out_lo,
    const int* __restrict__ scatter, int M)
{
    __shared__ __align__(16) char smem[32768];
    constexpr int AHI = 0, ALO = 8192, BHI = 16384, BLO = 24576;

    const int tid = threadIdx.x;
    const int wid = tid >> 5, lid = tid & 31;
    const int m0 = blockIdx.y * 128;
    const int n0 = blockIdx.x * 128;
    const int wm = wid & 3;        // m warp block (32 rows)
    const int wn = wid >> 2;       // n warp block (64 cols)
    const int NC = Kp / 32;
    const uint32_t sb = smem_u32(smem);

    // loader mapping: thread -> (row = tid>>1, half = tid&1 -> 16 elems)
    const int lrow = tid >> 1;
    const int lhalf = tid & 1;
    const int grA = m0 + lrow;
    const bool rowok = (grA < M);
    const float* a1row = nullptr; const float* a2row = nullptr;
    const __nv_bfloat16* ahrow = nullptr; const __nv_bfloat16* alrow = nullptr;
    if (rowok) {
        if (AMODE == 0) {
            int r1 = rowmap ? rowmap[grA] : grA;
            a1row = A1 + (size_t)r1 * lda1;
            if (A2) a2row = A2 + (size_t)grA * lda2;
        } else {
            ahrow = a_hi + (size_t)grA * 512;
            alrow = a_lo + (size_t)grA * 512;
        }
    }
    const __nv_bfloat16* bhrow = b_hi + (size_t)(n0 + lrow) * Kp;
    const __nv_bfloat16* blrow = b_lo + (size_t)(n0 + lrow) * Kp;

    const uint32_t st_off0 = sw64((uint32_t)(lrow * 64 + lhalf * 32));
    const uint32_t st_off1 = sw64((uint32_t)(lrow * 64 + lhalf * 32 + 16));

    float acc[2][8][4];
#pragma unroll
    for (int i = 0; i < 2; i++)
#pragma unroll
        for (int j = 0; j < 8; j++)
#pragma unroll
            for (int q = 0; q < 4; q++) acc[i][j][q] = 0.0f;

    // precomputed ldmatrix smem offsets
    const int fr = lid & 15;
    const uint32_t a_col = (uint32_t)((lid >> 4) * 16);
    uint32_t a_soff[2];
#pragma unroll
    for (int mi = 0; mi < 2; mi++)
        a_soff[mi] = (uint32_t)((wm * 32 + mi * 16 + fr) * 64) + a_col;
    const uint32_t b_row = (uint32_t)(wn * 64 + (lid & 7));
    const uint32_t b_col = (uint32_t)(((lid >> 3) & 1) * 16);

    for (int c = 0; c < NC; c++) {
        const int k0 = c * 32;
        __syncthreads();
        // ---- load A tile ----
        if (AMODE == 0) {
            const float* srcp; int valid;
            if (k0 < K1) { srcp = a1row + k0; valid = K1 - k0; }
            else         { srcp = a2row + (k0 - K1); valid = K - k0; }
            float v[16];
#pragma unroll
            for (int j = 0; j < 4; j++) {
                int cc = lhalf * 16 + j * 4;
                float4 f = make_float4(0.f, 0.f, 0.f, 0.f);
                if (rowok && cc + 4 <= valid) f = *reinterpret_cast<const float4*>(srcp + cc);
                v[j * 4 + 0] = f.x; v[j * 4 + 1] = f.y; v[j * 4 + 2] = f.z; v[j * 4 + 3] = f.w;
            }
            uint32_t hi[8], lo[8];
#pragma unroll
            for (int q = 0; q < 8; q++) {
                float a = v[q * 2], b = v[q * 2 + 1];
                float ah = __bfloat162float(__float2bfloat16_rn(a));
                float bh = __bfloat162float(__float2bfloat16_rn(b));
                hi[q] = pack_bf16(a, b);
                lo[q] = pack_bf16(a - ah, b - bh);
            }
            *reinterpret_cast<uint4*>(smem + AHI + st_off0) = make_uint4(hi[0], hi[1], hi[2], hi[3]);
            *reinterpret_cast<uint4*>(smem + AHI + st_off1) = make_uint4(hi[4], hi[5], hi[6], hi[7]);
            *reinterpret_cast<uint4*>(smem + ALO + st_off0) = make_uint4(lo[0], lo[1], lo[2], lo[3]);
            *reinterpret_cast<uint4*>(smem + ALO + st_off1) = make_uint4(lo[4], lo[5], lo[6], lo[7]);
        } else {
            uint4 h0 = make_uint4(0, 0, 0, 0), h1 = h0, l0 = h0, l1 = h0;
            if (rowok) {
                const __nv_bfloat16* ph = ahrow + k0 + lhalf * 16;
                const __nv_bfloat16* pl = alrow + k0 + lhalf * 16;
                h0 = *reinterpret_cast<const uint4*>(ph);
                h1 = *reinterpret_cast<const uint4*>(ph + 8);
                l0 = *reinterpret_cast<const uint4*>(pl);
                l1 = *reinterpret_cast<const uint4*>(pl + 8);
            }
            *reinterpret_cast<uint4*>(smem + AHI + st_off0) = h0;
            *reinterpret_cast<uint4*>(smem + AHI + st_off1) = h1;
            *reinterpret_cast<uint4*>(smem + ALO + st_off0) = l0;
            *reinterpret_cast<uint4*>(smem + ALO + st_off1) = l1;
        }
        // ---- load B tile ----
        {
            const __nv_bfloat16* ph = bhrow + k0 + lhalf * 16;
            const __nv_bfloat16* pl = blrow + k0 + lhalf * 16;
            uint4 h0 = *reinterpret_cast<const uint4*>(ph);
            uint4 h1 = *reinterpret_cast<const uint4*>(ph + 8);
            uint4 l0 = *reinterpret_cast<const uint4*>(pl);
            uint4 l1 = *reinterpret_cast<const uint4*>(pl + 8);
            *reinterpret_cast<uint4*>(smem + BHI + st_off0) = h0;
            *reinterpret_cast<uint4*>(smem + BHI + st_off1) = h1;
            *reinterpret_cast<uint4*>(smem + BLO + st_off0) = l0;
            *reinterpret_cast<uint4*>(smem + BLO + st_off1) = l1;
        }
        __syncthreads();

        // ---- compute ----
#pragma unroll
        for (int kk = 0; kk < 2; kk++) {
            uint32_t ah[2][4], al[2][4];
#pragma unroll
            for (int mi = 0; mi < 2; mi++) {
                uint32_t so = sw64(a_soff[mi] + (uint32_t)(kk * 32));
                LDMATRIX_X4(ah[mi][0], ah[mi][1], ah[mi][2], ah[mi][3], sb + AHI + so);
                LDMATRIX_X4(al[mi][0], al[mi][1], al[mi][2], al[mi][3], sb + ALO + so);
            }
#pragma unroll
            for (int ni = 0; ni < 8; ni++) {
                uint32_t so = sw64((b_row + (uint32_t)(ni * 8)) * 64 + b_col + (uint32_t)(kk * 32));
                uint32_t bh0, bh1, bl0, bl1;
                LDMATRIX_X2(bh0, bh1, sb + BHI + so);
                LDMATRIX_X2(bl0, bl1, sb + BLO + so);
#pragma unroll
                for (int mi = 0; mi < 2; mi++) {
                    float* d = acc[mi][ni];
                    mma_bf16(d[0], d[1], d[2], d[3],
                             ah[mi][0], ah[mi][1], ah[mi][2], ah[mi][3], bh0, bh1);
                    mma_bf16(d[0], d[1], d[2], d[3],
                             ah[mi][0], ah[mi][1], ah[mi][2], ah[mi][3], bl0, bl1);
                    mma_bf16(d[0], d[1], d[2], d[3],
                             al[mi][0], al[mi][1], al[mi][2], al[mi][3], bh0, bh1);
                }
            }
        }
    }

    // ---- epilogue ----
#pragma unroll
    for (int mi = 0; mi < 2; mi++) {
        int r0 = m0 + wm * 32 + mi * 16 + (lid >> 2);
        int r1 = r0 + 8;
        int or0 = -1, or1 = -1;
        if (EPI == 2) {
            if (r0 < M) or0 = scatter[r0];
            if (r1 < M) or1 = scatter[r1];
        }
#pragma unroll
        for (int ni = 0; ni < 8; ni++) {
            int gc = n0 + wn * 64 + ni * 8 + (lid & 3) * 2;
            float b0 = __ldg(bias + gc), b1 = __ldg(bias + gc + 1);
            float* d = acc[mi][ni];
            if (EPI == 0) {
                if (r0 < M) {
                    float2 v = make_float2(d[0] + b0, d[1] + b1);
                    *reinterpret_cast<float2*>(outf + (size_t)r0 * 512 + gc) = v;
                }
                if (r1 < M) {
                    float2 v = make_float2(d[2] + b0, d[3] + b1);
                    *reinterpret_cast<float2*>(outf + (size_t)r1 * 512 + gc) = v;
                }
            } else if (EPI == 1) {
                if (r0 < M) {
                    float a = gelu_exact(d[0] + b0), b = gelu_exact(d[1] + b1);
                    float ahf = __bfloat162float(__float2bfloat16_rn(a));
                    float bhf = __bfloat162float(__float2bfloat16_rn(b));
                    *reinterpret_cast<uint32_t*>(out_hi + (size_t)r0 * 512 + gc) = pack_bf16(a, b);
                    *reinterpret_cast<uint32_t*>(out_lo + (size_t)r0 * 512 + gc) = pack_bf16(a - ahf, b - bhf);
                }
                if (r1 < M) {
                    float a = gelu_exact(d[2] + b0), b = gelu_exact(d[3] + b1);
                    float ahf = __bfloat162float(__float2bfloat16_rn(a));
                    float bhf = __bfloat162float(__float2bfloat16_rn(b));
                    *reinterpret_cast<uint32_t*>(out_hi + (size_t)r1 * 512 + gc) = pack_bf16(a, b);
                    *reinterpret_cast<uint32_t*>(out_lo + (size_t)r1 * 512 + gc) = pack_bf16(a - ahf, b - bhf);
                }
            } else {
                if (or0 >= 0) {
                    float* p = outf + (size_t)or0 * 512 + gc;
                    asm volatile("red.global.add.v2.f32 [%0], {%1,%2};"
                                 :: "l"(p), "f"(d[0] + b0), "f"(d[1] + b1) : "memory");
                }
                if (or1 >= 0) {
                    float* p = outf + (size_t)or1 * 512 + gc;
                    asm volatile("red.global.add.v2.f32 [%0], {%1,%2};"
                                 :: "l"(p), "f"(d[2] + b0), "f"(d[3] + b1) : "memory");
                }
            }
        }
    }
}

// ---------------- edge update (gate + edge MLP + edge LN) ----------------
__global__ __launch_bounds__(256) void edge_update_kernel(
    const float* __restrict__ h,
    const float* __restrict__ edge_attr,
    const float* __restrict__ em_w1, const float* __restrict__ em_b1,
    const float* __restrict__ em_w2, const float* __restrict__ em_b2,
    const float* __restrict__ eg_w,  const float* __restrict__ eg_b,
    const float* __restrict__ en_g,  const float* __restrict__ en_b,
    const int* __restrict__ src, const int* __restrict__ dst,
    float* __restrict__ e_new)
{
    int warp = (blockIdx.x * blockDim.x + threadIdx.x) >> 5;
    int lane = threadIdx.x & 31;
    if (warp >= EE) return;
    int e = warp;
    const float* hs = h + (size_t)src[e] * HH;
    const float* hd = h + (size_t)dst[e] * HH;
    const float* ea = edge_attr + (size_t)e * EDD;
    const float4* w1 = reinterpret_cast<const float4*>(em_w1);

    float acc[17];
#pragma unroll
    for (int j = 0; j < 17; j++) acc[j] = 0.0f;

#define EDGE_FMA(I, Z) do {                                                   \
        const float4* wr = w1 + (size_t)(I) * 4;                              \
        float4 w0 = wr[0], w1v = wr[1], w2v = wr[2], w3v = wr[3];             \
        float z = (Z);                                                        \
        acc[0]  += z * w0.x;  acc[1]  += z * w0.y;  acc[2]  += z * w0.z;  acc[3]  += z * w0.w;  \
        acc[4]  += z * w1v.x; acc[5]  += z * w1v.y; acc[6]  += z * w1v.z; acc[7]  += z * w1v.w; \
        acc[8]  += z * w2v.x; acc[9]  += z * w2v.y; acc[10] += z * w2v.z; acc[11] += z * w2v.w; \
        acc[12] += z * w3v.x; acc[13] += z * w3v.y; acc[14] += z * w3v.z; acc[15] += z * w3v.w; \
    } while (0)

#pragma unroll
    for (int it = 0; it < 8; it++) {
        int i0 = it * 128 + lane * 4;
        float4 z4 = (i0 < 512) ? *reinterpret_cast<const float4*>(hs + i0)
                               : *reinterpret_cast<const float4*>(hd + i0 - 512);
        float4 g4 = *reinterpret_cast<const float4*>(eg_w + i0);
        EDGE_FMA(i0 + 0, z4.x); EDGE_FMA(i0 + 1, z4.y);
        EDGE_FMA(i0 + 2, z4.z); EDGE_FMA(i0 + 3, z4.w);
        acc[16] += z4.x * g4.x + z4.y * g4.y + z4.z * g4.z + z4.w * g4.w;
    }
    if (lane < 4) {
        int i0 = 1024 + lane * 4;
        float4 z4 = *reinterpret_cast<const float4*>(ea + lane * 4);
        float4 g4 = *reinterpret_cast<const float4*>(eg_w + i0);
        EDGE_FMA(i0 + 0, z4.x); EDGE_FMA(i0 + 1, z4.y);
        EDGE_FMA(i0 + 2, z4.z); EDGE_FMA(i0 + 3, z4.w);
        acc[16] += z4.x * g4.x + z4.y * g4.y + z4.z * g4.z + z4.w * g4.w;
    }
#undef EDGE_FMA

#pragma unroll
    for (int j = 0; j < 17; j++) {
#pragma unroll
        for (int o = 16; o > 0; o >>= 1)
            acc[j] += __shfl_xor_sync(0xffffffffu, acc[j], o);
    }

    float gate = 1.0f / (1.0f + expf(-(acc[16] + eg_b[0])));

    float gv = 0.0f;
    if (lane < 16) gv = gelu_exact(acc[lane] + em_b1[lane]);

    float delta = (lane < 16) ? em_b2[lane] : 0.0f;
#pragma unroll
    for (int k = 0; k < 16; k++) {
        float gk = __shfl_sync(0xffffffffu, gv, k);
        if (lane < 16) delta += gk * em_w2[k * 16 + lane];
    }

    float x = 0.0f;
    if (lane < 16) x = ea[lane] + EDGE_SCALE * gate * delta;

    float s = x;
#pragma unroll
    for (int o = 8; o > 0; o >>= 1) s += __shfl_xor_sync(0xffffffffu, s, o);
    float mu = s * (1.0f / 16.0f);
    float d = x - mu;
    float v = d * d;
#pragma unroll
    for (int o = 8; o > 0; o >>= 1) v += __shfl_xor_sync(0xffffffffu, v, o);
    float r = rsqrtf(v * (1.0f / 16.0f) + LNEPS);
    if (lane < 16)
        e_new[(size_t)e * EDD + lane] = d * r * en_g[lane] + en_b[lane];
}

// ---------------- residual + LayerNorm over 512 ----------------
__global__ __launch_bounds__(128) void node_out_kernel(
    const float* __restrict__ h, const float* __restrict__ h2,
    const float* __restrict__ g, const float* __restrict__ b,
    float* __restrict__ out)
{
    int n = blockIdx.x;
    int t = threadIdx.x;
    const float* hr  = h  + (size_t)n * HH;
    const float* h2r = h2 + (size_t)n * HH;

    float x[4];
    float s = 0.0f;
#pragma unroll
    for (int i = 0; i < 4; i++) {
        int c = t + 128 * i;
        x[i] = hr[c] + h2r[c];
        s += x[i];
    }
    __shared__ float red[4];
#pragma unroll
    for (int o = 16; o > 0; o >>= 1) s += __shfl_xor_sync(0xffffffffu, s, o);
    int warp = t >> 5, lane = t & 31;
    if (lane == 0) red[warp] = s;
    __syncthreads();
    float mu = (red[0] + red[1] + red[2] + red[3]) * (1.0f / 512.0f);

    float v = 0.0f;
#pragma unroll
    for (int i = 0; i < 4; i++) { float d = x[i] - mu; v += d * d; }
#pragma unroll
    for (int o = 16; o > 0; o >>= 1) v += __shfl_xor_sync(0xffffffffu, v, o);
    __syncthreads();
    if (lane == 0) red[warp] = v;
    __syncthreads();
    float var = (red[0] + red[1] + red[2] + red[3]) * (1.0f / 512.0f);
    float r = rsqrtf(var + LNEPS);

#pragma unroll
    for (int i = 0; i < 4; i++) {
        int c = t + 128 * i;
        out[(size_t)n * HH + c] = (x[i] - mu) * r * g[c] + b[c];
    }
}

// ---------------- launch ----------------
extern "C" void kernel_launch(void* const* d_in, const int* in_sizes, int n_in,
                              void* d_out, int out_size)
{
    const float* h       = (const float*)d_in[0];
    const float* edge_a  = (const float*)d_in[1];
    const float* msg_w1  = (const float*)d_in[2];
    const float* msg_b1  = (const float*)d_in[3];
    const float* msg_w2  = (const float*)d_in[4];
    const float* msg_b2  = (const float*)d_in[5];
    const float* upd_w1  = (const float*)d_in[6];
    const float* upd_b1  = (const float*)d_in[7];
    const float* upd_w2  = (const float*)d_in[8];
    const float* upd_b2  = (const float*)d_in[9];
    const float* norm_g  = (const float*)d_in[10];
    const float* norm_b  = (const float*)d_in[11];
    const float* em_w1   = (const float*)d_in[12];
    const float* em_b1   = (const float*)d_in[13];
    const float* em_w2   = (const float*)d_in[14];
    const float* em_b2   = (const float*)d_in[15];
    const float* eg_w    = (const float*)d_in[16];
    const float* eg_b    = (const float*)d_in[17];
    const float* en_g    = (const float*)d_in[18];
    const float* en_b    = (const float*)d_in[19];
    const int*   eindex  = (const int*)d_in[20];
    const int*   src = eindex;
    const int*   dst = eindex + EE;

    float* h_out = (float*)d_out;
    float* e_new = (float*)d_out + (size_t)NN * HH;

    __nv_bfloat16 *Thi, *Tlo, *Uhi, *Ulo, *w1hi, *w1lo, *w2hi, *w2lo, *u1hi, *u1lo, *u2hi, *u2lo;
    float *agg, *h2;
    cudaGetSymbolAddress((void**)&Thi, g_Thi);  cudaGetSymbolAddress((void**)&Tlo, g_Tlo);
    cudaGetSymbolAddress((void**)&Uhi, g_Uhi);  cudaGetSymbolAddress((void**)&Ulo, g_Ulo);
    cudaGetSymbolAddress((void**)&agg, g_agg);  cudaGetSymbolAddress((void**)&h2,  g_h2);
    cudaGetSymbolAddress((void**)&w1hi, g_w1hi); cudaGetSymbolAddress((void**)&w1lo, g_w1lo);
    cudaGetSymbolAddress((void**)&w2hi, g_w2hi); cudaGetSymbolAddress((void**)&w2lo, g_w2lo);
    cudaGetSymbolAddress((void**)&u1hi, g_u1hi); cudaGetSymbolAddress((void**)&u1lo, g_u1lo);
    cudaGetSymbolAddress((void**)&u2hi, g_u2hi); cudaGetSymbolAddress((void**)&u2lo, g_u2lo);

    // weight prep (transpose + bf16 hi/lo split)
    dim3 wb(32, 8);
    wsplit_kernel<<<dim3(576 / 32, 16), wb>>>(msg_w1, 528, 576, w1hi, w1lo);
    wsplit_kernel<<<dim3(512 / 32, 16), wb>>>(msg_w2, 512, 512, w2hi, w2lo);
    wsplit_kernel<<<dim3(1024 / 32, 16), wb>>>(upd_w1, 1024, 1024, u1hi, u1lo);
    wsplit_kernel<<<dim3(512 / 32, 16), wb>>>(upd_w2, 512, 512, u2hi, u2lo);

    // zero aggregation buffer
    zero_kernel<<<(NN * HH / 4 + 255) / 256, 256>>>((float4*)agg, NN * HH / 4);

    // edge update -> e_new (into d_out)
    edge_update_kernel<<<EE / 8, 256>>>(h, edge_a, em_w1, em_b1, em_w2, em_b2,
                                        eg_w, eg_b, en_g, en_b, src, dst, e_new);

    // stage 3: T = gelu([h[src] | e_new] @ msg_w1 + b1)   (E x 528 x 512) -> bf16 hi/lo
    mma_gemm<0, 1><<<dim3(4, EE / 128), 256>>>(
        h, e_new, HH, EDD, HH, 528, src,
        nullptr, nullptr, w1hi, w1lo, 576, msg_b1,
        nullptr, Thi, Tlo, nullptr, EE);

    // stage 4: agg[dst] += T @ msg_w2 + b2                (E x 512 x 512, red scatter)
    mma_gemm<1, 2><<<dim3(4, EE / 128), 256>>>(
        nullptr, nullptr, 0, 0, 512, 512, nullptr,
        Thi, Tlo, w2hi, w2lo, 512, msg_b2,
        agg, nullptr, nullptr, dst, EE);

    // stage 5: U = gelu([h | agg] @ upd_w1 + b1)          (N x 1024 x 512) -> bf16 hi/lo
    mma_gemm<0, 1><<<dim3(4, (NN + 127) / 128), 256>>>(
        h, agg, HH, HH, HH, 1024, nullptr,
        nullptr, nullptr, u1hi, u1lo, 1024, upd_b1,
        nullptr, Uhi, Ulo, nullptr, NN);

    // stage 6: h2 = U @ upd_w2 + b2                       (N x 512 x 512) -> fp32
    mma_gemm<1, 0><<<dim3(4, (NN + 127) / 128), 256>>>(
        nullptr, nullptr, 0, 0, 512, 512, nullptr,
        Uhi, Ulo, u2hi, u2lo, 512, upd_b2,
        h2, nullptr, nullptr, nullptr, NN);

    // h_out = LN(h + h2)
    node_out_kernel<<<NN, 128>>>(h, h2, norm_g, norm_b, h_out);
}

// round 8
// speedup vs baseline: 1.7186x; 1.1869x over previous
#include <cuda_runtime.h>
#include <cuda_bf16.h>
#include <math.h>
#include <stdint.h>

#define NN 10000
#define EE 160000
#define HH 512
#define EDD 16
#define LNEPS 1e-5f
#define EDGE_SCALE 0.1f

// ---------------- scratch (no allocations allowed) ----------------
__device__ __nv_bfloat16 g_Thi[(size_t)EE * HH];
__device__ __nv_bfloat16 g_Tlo[(size_t)EE * HH];
__device__ float         g_agg[(size_t)NN * HH];
__device__ __nv_bfloat16 g_Uhi[(size_t)NN * HH];
__device__ __nv_bfloat16 g_Ulo[(size_t)NN * HH];
__device__ float         g_h2[(size_t)NN * HH];
__device__ __nv_bfloat16 g_hhi[(size_t)NN * HH];
__device__ __nv_bfloat16 g_hlo[(size_t)NN * HH];
__device__ __nv_bfloat16 g_ahi[(size_t)NN * HH];
__device__ __nv_bfloat16 g_alo[(size_t)NN * HH];
__device__ __nv_bfloat16 g_ehi[(size_t)EE * EDD];
__device__ __nv_bfloat16 g_elo[(size_t)EE * EDD];
// transposed + split weights: [512][Kp] bf16 (n-major, k contiguous)
__device__ __nv_bfloat16 g_w1hi[512 * 576],  g_w1lo[512 * 576];   // msg_w1 (K=528,Kp=576)
__device__ __nv_bfloat16 g_w2hi[512 * 512],  g_w2lo[512 * 512];   // msg_w2
__device__ __nv_bfloat16 g_u1hi[512 * 1024], g_u1lo[512 * 1024];  // upd_w1
__device__ __nv_bfloat16 g_u2hi[512 * 512],  g_u2lo[512 * 512];   // upd_w2

__device__ __forceinline__ float gelu_exact(float x) {
    return 0.5f * x * (1.0f + erff(x * 0.70710678118654752440f));
}

__device__ __forceinline__ uint32_t smem_u32(const void* p) {
    uint32_t a;
    asm("{ .reg .u64 t; cvta.to.shared.u64 t, %1; cvt.u32.u64 %0, t; }" : "=r"(a) : "l"(p));
    return a;
}

// swizzle: XOR bits[4:5] with bits[7:8] -> conflict-free 16B ldmatrix/STS on 64B rows
__device__ __forceinline__ uint32_t sw64(uint32_t x) {
    return x ^ (((x >> 7) & 3u) << 4);
}

__device__ __forceinline__ uint32_t pack_bf16(float a, float b) {
    __nv_bfloat162 p = __floats2bfloat162_rn(a, b);
    return *reinterpret_cast<uint32_t*>(&p);
}

#define LDMATRIX_X4(r0, r1, r2, r3, addr) \
    asm volatile("ldmatrix.sync.aligned.m8n8.x4.shared.b16 {%0,%1,%2,%3}, [%4];" \
                 : "=r"(r0), "=r"(r1), "=r"(r2), "=r"(r3) : "r"(addr))

__device__ __forceinline__ void mma_bf16(float& d0, float& d1, float& d2, float& d3,
                                         uint32_t a0, uint32_t a1, uint32_t a2, uint32_t a3,
                                         uint32_t b0, uint32_t b1) {
    asm volatile(
        "mma.sync.aligned.m16n8k16.row.col.f32.bf16.bf16.f32 "
        "{%0,%1,%2,%3}, {%4,%5,%6,%7}, {%8,%9}, {%0,%1,%2,%3};"
        : "+f"(d0), "+f"(d1), "+f"(d2), "+f"(d3)
        : "r"(a0), "r"(a1), "r"(a2), "r"(a3), "r"(b0), "r"(b1));
}

__device__ __forceinline__ void cp16(uint32_t dst, const void* src, uint32_t ss) {
    asm volatile("cp.async.cg.shared.global [%0], [%1], 16, %2;"
                 :: "r"(dst), "l"(src), "r"(ss) : "memory");
}
#define CP_COMMIT() asm volatile("cp.async.commit_group;" ::: "memory")
#define CP_WAIT(n)  asm volatile("cp.async.wait_group %0;" :: "n"(n) : "memory")

// ---------------- weight transpose + hi/lo split ----------------
__global__ void wsplit_kernel(const float* __restrict__ W, int K, int Kp,
                              __nv_bfloat16* __restrict__ ohi,
                              __nv_bfloat16* __restrict__ olo) {
    __shared__ float t[32][33];
    int kb = blockIdx.x * 32, nb = blockIdx.y * 32;
    int tx = threadIdx.x, ty = threadIdx.y;  // 32 x 8
#pragma unroll
    for (int r = 0; r < 4; r++) {
        int k = kb + ty + r * 8;
        t[ty + r * 8][tx] = (k < K) ? W[(size_t)k * 512 + nb + tx] : 0.0f;
    }
    __syncthreads();
#pragma unroll
    for (int r = 0; r < 4; r++) {
        int n = nb + ty + r * 8;
        int k = kb + tx;
        float v = t[tx][ty + r * 8];
        __nv_bfloat16 h = __float2bfloat16_rn(v);
        ohi[(size_t)n * Kp + k] = h;
        olo[(size_t)n * Kp + k] = __float2bfloat16_rn(v - __bfloat162float(h));
    }
}

// ---------------- fp32 -> bf16 hi/lo elementwise split ----------------
__global__ void fsplit_kernel(const float4* __restrict__ in,
                              uint2* __restrict__ oh, uint2* __restrict__ ol, int n4) {
    int i = blockIdx.x * blockDim.x + threadIdx.x;
    if (i >= n4) return;
    float4 f = in[i];
    float hx = __bfloat162float(__float2bfloat16_rn(f.x));
    float hy = __bfloat162float(__float2bfloat16_rn(f.y));
    float hz = __bfloat162float(__float2bfloat16_rn(f.z));
    float hw = __bfloat162float(__float2bfloat16_rn(f.w));
    oh[i] = make_uint2(pack_bf16(f.x, f.y), pack_bf16(f.z, f.w));
    ol[i] = make_uint2(pack_bf16(f.x - hx, f.y - hy), pack_bf16(f.z - hz, f.w - hw));
}

// ---------------- zero ----------------
__global__ void zero_kernel(float4* __restrict__ p, int n4) {
    int i = blockIdx.x * blockDim.x + threadIdx.x;
    if (i < n4) p[i] = make_float4(0.f, 0.f, 0.f, 0.f);
}

// ---------------- HMMA GEMM, cp.async double-buffered ----------------
// C[M x 512]; CTA tile 128m x 128n; BK=32; 3-pass bf16 hi/lo.
// A rows: k < 32*C1 from a1 (rowmap gather, stride s1); after that from a2
// (identity rows, stride s2 elems, tb2 valid bytes total); zeros beyond.
// EPI 0: fp32 store (+bias); EPI 1: gelu -> bf16 hi/lo; EPI 2: red.add scatter (+bias).
template <int EPI>
__global__ __launch_bounds__(256) void mma_gemm(
    const __nv_bfloat16* __restrict__ a1h, const __nv_bfloat16* __restrict__ a1l,
    int s1, const int* __restrict__ map1, int C1,
    const __nv_bfloat16* __restrict__ a2h, const __nv_bfloat16* __restrict__ a2l,
    int s2, int tb2,
    const __nv_bfloat16* __restrict__ bh, const __nv_bfloat16* __restrict__ bl, int Kp,
    const float* __restrict__ bias,
    float* __restrict__ outf,
    __nv_bfloat16* __restrict__ out_hi, __nv_bfloat16* __restrict__ out_lo,
    const int* __restrict__ scatter, int M)
{
    extern __shared__ __align__(16) char smem[];
    constexpr int AHI = 0, ALO = 8192, BHI = 16384, BLO = 24576, BUF = 32768;

    const int tid = threadIdx.x;
    const int wid = tid >> 5, lid = tid & 31;
    const int m0 = blockIdx.y * 128;
    const int n0 = blockIdx.x * 128;
    const int wm = wid & 3;
    const int wn = wid >> 2;
    const int NC = Kp / 32;
    const uint32_t sb = smem_u32(smem);

    // loader mapping: 2 threads per row
    const int lrow = tid >> 1;
    const int lh32 = (tid & 1) * 32;      // byte offset of this thread's 32B half-row
    const int grA = m0 + lrow;
    const bool rowok = (grA < M);
    int r1 = 0;
    if (rowok) r1 = map1 ? map1[grA] : grA;
    const char* a1hp = (const char*)(a1h + (size_t)r1 * s1);
    const char* a1lp = (const char*)(a1l + (size_t)r1 * s1);
    const char* a2hp = (const char*)(a2h + (size_t)grA * (rowok ? s2 : 0));
    const char* a2lp = (const char*)(a2l + (size_t)grA * (rowok ? s2 : 0));
    const char* bhp = (const char*)(bh + (size_t)(n0 + lrow) * Kp);
    const char* blp = (const char*)(bl + (size_t)(n0 + lrow) * Kp);

    const uint32_t dA0 = sw64((uint32_t)(lrow * 64 + lh32));
    const uint32_t dA1 = sw64((uint32_t)(lrow * 64 + lh32 + 16));

    auto load_chunk = [&](int c, int bufi) {
        uint32_t base = sb + bufi * BUF;
        const char *sh, *sl;
        int valid;
        if (c < C1) {
            sh = a1hp + c * 64; sl = a1lp + c * 64;
            valid = rowok ? 64 : 0;
        } else {
            int off = (c - C1) * 64;
            sh = a2hp + off; sl = a2lp + off;
            int v = tb2 - off;
            v = v < 0 ? 0 : (v > 64 ? 64 : v);
            valid = rowok ? v : 0;
        }
        int ss0 = valid - lh32;      ss0 = ss0 < 0 ? 0 : (ss0 > 16 ? 16 : ss0);
        int ss1 = valid - lh32 - 16; ss1 = ss1 < 0 ? 0 : (ss1 > 16 ? 16 : ss1);
        cp16(base + AHI + dA0, sh + lh32,      (uint32_t)ss0);
        cp16(base + AHI + dA1, sh + lh32 + 16, (uint32_t)ss1);
        cp16(base + ALO + dA0, sl + lh32,      (uint32_t)ss0);
        cp16(base + ALO + dA1, sl + lh32 + 16, (uint32_t)ss1);
        const char* bsh = bhp + c * 64;
        const char* bsl = blp + c * 64;
        cp16(base + BHI + dA0, bsh + lh32,      16u);
        cp16(base + BHI + dA1, bsh + lh32 + 16, 16u);
        cp16(base + BLO + dA0, bsl + lh32,      16u);
        cp16(base + BLO + dA1, bsl + lh32 + 16, 16u);
    };

    float acc[2][8][4];
#pragma unroll
    for (int i = 0; i < 2; i++)
#pragma unroll
        for (int j = 0; j < 8; j++)
#pragma unroll
            for (int q = 0; q < 4; q++) acc[i][j][q] = 0.0f;

    // ldmatrix offsets
    const int fr = lid & 15;
    const uint32_t a_col = (uint32_t)((lid >> 4) * 16);
    uint32_t a_soff[2];
#pragma unroll
    for (int mi = 0; mi < 2; mi++)
        a_soff[mi] = (uint32_t)((wm * 32 + mi * 16 + fr) * 64) + a_col;
    // B x4: lanes 0-15 -> tile ni, 16-31 -> tile ni+1
    const uint32_t b_base = (uint32_t)((wn * 64 + (lid & 7) + ((lid >> 4) & 1) * 8) * 64 +
                                       (((lid >> 3) & 1) * 16));

    load_chunk(0, 0);
    CP_COMMIT();

    for (int c = 0; c < NC; c++) {
        if (c + 1 < NC) { load_chunk(c + 1, (c + 1) & 1); CP_COMMIT(); CP_WAIT(1); }
        else           { CP_WAIT(0); }
        __syncthreads();
        uint32_t bufb = sb + (c & 1) * BUF;

#pragma unroll
        for (int kk = 0; kk < 2; kk++) {
            uint32_t ah[2][4], al[2][4];
#pragma unroll
            for (int mi = 0; mi < 2; mi++) {
                uint32_t so = sw64(a_soff[mi] + (uint32_t)(kk * 32));
                LDMATRIX_X4(ah[mi][0], ah[mi][1], ah[mi][2], ah[mi][3], bufb + AHI + so);
                LDMATRIX_X4(al[mi][0], al[mi][1], al[mi][2], al[mi][3], bufb + ALO + so);
            }
#pragma unroll
            for (int ni = 0; ni < 8; ni += 2) {
                uint32_t so = sw64(b_base + (uint32_t)(ni * 8 * 64) + (uint32_t)(kk * 32));
                uint32_t bh0, bh1, bh2, bh3, bl0, bl1, bl2, bl3;
                LDMATRIX_X4(bh0, bh1, bh2, bh3, bufb + BHI + so);
                LDMATRIX_X4(bl0, bl1, bl2, bl3, bufb + BLO + so);
#pragma unroll
                for (int mi = 0; mi < 2; mi++) {
                    float* d = acc[mi][ni];
                    mma_bf16(d[0], d[1], d[2], d[3],
                             ah[mi][0], ah[mi][1], ah[mi][2], ah[mi][3], bh0, bh1);
                    mma_bf16(d[0], d[1], d[2], d[3],
                             ah[mi][0], ah[mi][1], ah[mi][2], ah[mi][3], bl0, bl1);
                    mma_bf16(d[0], d[1], d[2], d[3],
                             al[mi][0], al[mi][1], al[mi][2], al[mi][3], bh0, bh1);
                    float* e = acc[mi][ni + 1];
                    mma_bf16(e[0], e[1], e[2], e[3],
                             ah[mi][0], ah[mi][1], ah[mi][2], ah[mi][3], bh2, bh3);
                    mma_bf16(e[0], e[1], e[2], e[3],
                             ah[mi][0], ah[mi][1], ah[mi][2], ah[mi][3], bl2, bl3);
                    mma_bf16(e[0], e[1], e[2], e[3],
                             al[mi][0], al[mi][1], al[mi][2], al[mi][3], bh2, bh3);
                }
            }
        }
        __syncthreads();
    }

    // ---- epilogue ----
#pragma unroll
    for (int mi = 0; mi < 2; mi++) {
        int r0 = m0 + wm * 32 + mi * 16 + (lid >> 2);
        int r1o = r0 + 8;
        int or0 = -1, or1 = -1;
        if (EPI == 2) {
            if (r0 < M) or0 = scatter[r0];
            if (r1o < M) or1 = scatter[r1o];
        }
#pragma unroll
        for (int ni = 0; ni < 8; ni++) {
            int gc = n0 + wn * 64 + ni * 8 + (lid & 3) * 2;
            float b0 = __ldg(bias + gc), b1 = __ldg(bias + gc + 1);
            float* d = acc[mi][ni];
            if (EPI == 0) {
                if (r0 < M)
                    *reinterpret_cast<float2*>(outf + (size_t)r0 * 512 + gc) =
                        make_float2(d[0] + b0, d[1] + b1);
                if (r1o < M)
                    *reinterpret_cast<float2*>(outf + (size_t)r1o * 512 + gc) =
                        make_float2(d[2] + b0, d[3] + b1);
            } else if (EPI == 1) {
                if (r0 < M) {
                    float a = gelu_exact(d[0] + b0), b = gelu_exact(d[1] + b1);
                    float ah = __bfloat162float(__float2bfloat16_rn(a));
                    float bh2 = __bfloat162float(__float2bfloat16_rn(b));
                    *reinterpret_cast<uint32_t*>(out_hi + (size_t)r0 * 512 + gc) = pack_bf16(a, b);
                    *reinterpret_cast<uint32_t*>(out_lo + (size_t)r0 * 512 + gc) = pack_bf16(a - ah, b - bh2);
                }
                if (r1o < M) {
                    float a = gelu_exact(d[2] + b0), b = gelu_exact(d[3] + b1);
                    float ah = __bfloat162float(__float2bfloat16_rn(a));
                    float bh2 = __bfloat162float(__float2bfloat16_rn(b));
                    *reinterpret_cast<uint32_t*>(out_hi + (size_t)r1o * 512 + gc) = pack_bf16(a, b);
                    *reinterpret_cast<uint32_t*>(out_lo + (size_t)r1o * 512 + gc) = pack_bf16(a - ah, b - bh2);
                }
            } else {
                if (or0 >= 0) {
                    float* p = outf + (size_t)or0 * 512 + gc;
                    asm volatile("red.global.add.v2.f32 [%0], {%1,%2};"
                                 :: "l"(p), "f"(d[0] + b0), "f"(d[1] + b1) : "memory");
                }
                if (or1 >= 0) {
                    float* p = outf + (size_t)or1 * 512 + gc;
                    asm volatile("red.global.add.v2.f32 [%0], {%1,%2};"
                                 :: "l"(p), "f"(d[2] + b0), "f"(d[3] + b1) : "memory");
                }
            }
        }
    }
}

// ---------------- edge update: SMEM-cached weights, 2 edges per warp ----------------
// wT layout: [17][1040] fp32 in SMEM (row j = output dim; j=16 is gate column).
__global__ __launch_bounds__(256) void edge_update_kernel(
    const float* __restrict__ h,
    const float* __restrict__ edge_attr,
    const float* __restrict__ em_w1, const float* __restrict__ em_b1,
    const float* __restrict__ em_w2, const float* __restrict__ em_b2,
    const float* __restrict__ eg_w,  const float* __restrict__ eg_b,
    const float* __restrict__ en_g,  const float* __restrict__ en_b,
    const int* __restrict__ src, const int* __restrict__ dst,
    float* __restrict__ e_new,
    __nv_bfloat16* __restrict__ e_hi, __nv_bfloat16* __restrict__ e_lo)
{
    extern __shared__ __align__(16) float wt[];   // 17 * 1040 floats
    const int tid = threadIdx.x;
    const int wid = tid >> 5, lane = tid & 31;

    // fill weights (transposed)
    for (int t = tid; t < 1040 * 16; t += 256) {
        int i = t >> 4, j = t & 15;
        wt[j * 1040 + i] = em_w1[t];
    }
    for (int t = tid; t < 1040; t += 256)
        wt[16 * 1040 + t] = eg_w[t];
    __syncthreads();

    const int half = lane >> 4;      // 0: edge0, 1: edge1
    const int loc  = lane & 15;

    const int ctaBase = blockIdx.x * 128;
#pragma unroll 1
    for (int it = 0; it < 8; it++) {
        int e0 = ctaBase + wid * 16 + it * 2;
        int e1 = e0 + 1;
        const float* hs0 = h + (size_t)src[e0] * HH;
        const float* hd0 = h + (size_t)dst[e0] * HH;
        const float* hs1 = h + (size_t)src[e1] * HH;
        const float* hd1 = h + (size_t)dst[e1] * HH;

        float acc0[17], acc1[17];
#pragma unroll
        for (int j = 0; j < 17; j++) { acc0[j] = 0.0f; acc1[j] = 0.0f; }

#pragma unroll
        for (int blk = 0; blk < 8; blk++) {
            int i0 = blk * 128 + lane * 4;
            float4 z0 = (i0 < 512) ? *reinterpret_cast<const float4*>(hs0 + i0)
                                   : *reinterpret_cast<const float4*>(hd0 + i0 - 512);
            float4 z1 = (i0 < 512) ? *reinterpret_cast<const float4*>(hs1 + i0)
                                   : *reinterpret_cast<const float4*>(hd1 + i0 - 512);
#pragma unroll
            for (int j = 0; j < 17; j++) {
                float4 w = *reinterpret_cast<const float4*>(&wt[j * 1040 + i0]);
                acc0[j] += z0.x * w.x + z0.y * w.y + z0.z * w.z + z0.w * w.w;
                acc1[j] += z1.x * w.x + z1.y * w.y + z1.z * w.z + z1.w * w.w;
            }
        }
        if (lane < 4) {
            int i0 = 1024 + lane * 4;
            float4 z0 = *reinterpret_cast<const float4*>(edge_attr + (size_t)e0 * EDD + lane * 4);
            float4 z1 = *reinterpret_cast<const float4*>(edge_attr + (size_t)e1 * EDD + lane * 4);
#pragma unroll
            for (int j = 0; j < 17; j++) {
                float4 w = *reinterpret_cast<const float4*>(&wt[j * 1040 + i0]);
                acc0[j] += z0.x * w.x + z0.y * w.y + z0.z * w.z + z0.w * w.w;
                acc1[j] += z1.x * w.x + z1.y * w.y + z1.z * w.z + z1.w * w.w;
            }
        }

#pragma unroll
        for (int j = 0; j < 17; j++) {
#pragma unroll
            for (int o = 16; o > 0; o >>= 1) {
                acc0[j] += __shfl_xor_sync(0xffffffffu, acc0[j], o);
                acc1[j] += __shfl_xor_sync(0xffffffffu, acc1[j], o);
            }
        }

        // per-half: my edge's sums
        int e = half ? e1 : e0;
        float a16 = half ? acc1[16] : acc0[16];
        float aj  = half ? acc1[loc] : acc0[loc];
        float gate = 1.0f / (1.0f + expf(-(a16 + eg_b[0])));
        float gv = gelu_exact(aj + em_b1[loc]);

        float delta = em_b2[loc];
#pragma unroll
        for (int k = 0; k < 16; k++) {
            float gk = __shfl_sync(0xffffffffu, gv, k + (half << 4));
            delta += gk * em_w2[k * 16 + loc];
        }

        float x = edge_attr[(size_t)e * EDD + loc] + EDGE_SCALE * gate * delta;

        float s = x;
#pragma unroll
        for (int o = 8; o > 0; o >>= 1) s += __shfl_xor_sync(0xffffffffu, s, o);
        float mu = s * (1.0f / 16.0f);
        float d = x - mu;
        float v = d * d;
#pragma unroll
        for (int o = 8; o > 0; o >>= 1) v += __shfl_xor_sync(0xffffffffu, v, o);
        float r = rsqrtf(v * (1.0f / 16.0f) + LNEPS);
        float val = d * r * en_g[loc] + en_b[loc];
        e_new[(size_t)e * EDD + loc] = val;
        __nv_bfloat16 vh = __float2bfloat16_rn(val);
        e_hi[(size_t)e * EDD + loc] = vh;
        e_lo[(size_t)e * EDD + loc] = __float2bfloat16_rn(val - __bfloat162float(vh));
    }
}

// ---------------- residual + LayerNorm over 512 ----------------
__global__ __launch_bounds__(128) void node_out_kernel(
    const float* __restrict__ h, const float* __restrict__ h2,
    const float* __restrict__ g, const float* __restrict__ b,
    float* __restrict__ out)
{
    int n = blockIdx.x;
    int t = threadIdx.x;
    const float* hr  = h  + (size_t)n * HH;
    const float* h2r = h2 + (size_t)n * HH;

    float x[4];
    float s = 0.0f;
#pragma unroll
    for (int i = 0; i < 4; i++) {
        int c = t + 128 * i;
        x[i] = hr[c] + h2r[c];
        s += x[i];
    }
    __shared__ float red[4];
#pragma unroll
    for (int o = 16; o > 0; o >>= 1) s += __shfl_xor_sync(0xffffffffu, s, o);
    int warp = t >> 5, lane = t & 31;
    if (lane == 0) red[warp] = s;
    __syncthreads();
    float mu = (red[0] + red[1] + red[2] + red[3]) * (1.0f / 512.0f);

    float v = 0.0f;
#pragma unroll
    for (int i = 0; i < 4; i++) { float d = x[i] - mu; v += d * d; }
#pragma unroll
    for (int o = 16; o > 0; o >>= 1) v += __shfl_xor_sync(0xffffffffu, v, o);
    __syncthreads();
    if (lane == 0) red[warp] = v;
    __syncthreads();
    float var = (red[0] + red[1] + red[2] + red[3]) * (1.0f / 512.0f);
    float r = rsqrtf(var + LNEPS);

#pragma unroll
    for (int i = 0; i < 4; i++) {
        int c = t + 128 * i;
        out[(size_t)n * HH + c] = (x[i] - mu) * r * g[c] + b[c];
    }
}

// ---------------- launch ----------------
extern "C" void kernel_launch(void* const* d_in, const int* in_sizes, int n_in,
                              void* d_out, int out_size)
{
    const float* h       = (const float*)d_in[0];
    const float* edge_a  = (const float*)d_in[1];
    const float* msg_w1  = (const float*)d_in[2];
    const float* msg_b1  = (const float*)d_in[3];
    const float* msg_w2  = (const float*)d_in[4];
    const float* msg_b2  = (const float*)d_in[5];
    const float* upd_w1  = (const float*)d_in[6];
    const float* upd_b1  = (const float*)d_in[7];
    const float* upd_w2  = (const float*)d_in[8];
    const float* upd_b2  = (const float*)d_in[9];
    const float* norm_g  = (const float*)d_in[10];
    const float* norm_b  = (const float*)d_in[11];
    const float* em_w1   = (const float*)d_in[12];
    const float* em_b1   = (const float*)d_in[13];
    const float* em_w2   = (const float*)d_in[14];
    const float* em_b2   = (const float*)d_in[15];
    const float* eg_w    = (const float*)d_in[16];
    const float* eg_b    = (const float*)d_in[17];
    const float* en_g    = (const float*)d_in[18];
    const float* en_b    = (const float*)d_in[19];
    const int*   eindex  = (const int*)d_in[20];
    const int*   src = eindex;
    const int*   dst = eindex + EE;

    float* h_out = (float*)d_out;
    float* e_new = (float*)d_out + (size_t)NN * HH;

    __nv_bfloat16 *Thi, *Tlo, *Uhi, *Ulo, *hhi, *hlo, *ahi, *alo, *ehi, *elo;
    __nv_bfloat16 *w1hi, *w1lo, *w2hi, *w2lo, *u1hi, *u1lo, *u2hi, *u2lo;
    float *agg, *h2;
    cudaGetSymbolAddress((void**)&Thi, g_Thi);  cudaGetSymbolAddress((void**)&Tlo, g_Tlo);
    cudaGetSymbolAddress((void**)&Uhi, g_Uhi);  cudaGetSymbolAddress((void**)&Ulo, g_Ulo);
    cudaGetSymbolAddress((void**)&agg, g_agg);  cudaGetSymbolAddress((void**)&h2,  g_h2);
    cudaGetSymbolAddress((void**)&hhi, g_hhi);  cudaGetSymbolAddress((void**)&hlo, g_hlo);
    cudaGetSymbolAddress((void**)&ahi, g_ahi);  cudaGetSymbolAddress((void**)&alo, g_alo);
    cudaGetSymbolAddress((void**)&ehi, g_ehi);  cudaGetSymbolAddress((void**)&elo, g_elo);
    cudaGetSymbolAddress((void**)&w1hi, g_w1hi); cudaGetSymbolAddress((void**)&w1lo, g_w1lo);
    cudaGetSymbolAddress((void**)&w2hi, g_w2hi); cudaGetSymbolAddress((void**)&w2lo, g_w2lo);
    cudaGetSymbolAddress((void**)&u1hi, g_u1hi); cudaGetSymbolAddress((void**)&u1lo, g_u1lo);
    cudaGetSymbolAddress((void**)&u2hi, g_u2hi); cudaGetSymbolAddress((void**)&u2lo, g_u2lo);

    cudaFuncSetAttribute(mma_gemm<0>, cudaFuncAttributeMaxDynamicSharedMemorySize, 65536);
    cudaFuncSetAttribute(mma_gemm<1>, cudaFuncAttributeMaxDynamicSharedMemorySize, 65536);
    cudaFuncSetAttribute(mma_gemm<2>, cudaFuncAttributeMaxDynamicSharedMemorySize, 65536);
    cudaFuncSetAttribute(edge_update_kernel, cudaFuncAttributeMaxDynamicSharedMemorySize, 72000);

    // weight prep
    dim3 wb(32, 8);
    wsplit_kernel<<<dim3(576 / 32, 16), wb>>>(msg_w1, 528, 576, w1hi, w1lo);
    wsplit_kernel<<<dim3(512 / 32, 16), wb>>>(msg_w2, 512, 512, w2hi, w2lo);
    wsplit_kernel<<<dim3(1024 / 32, 16), wb>>>(upd_w1, 1024, 1024, u1hi, u1lo);
    wsplit_kernel<<<dim3(512 / 32, 16), wb>>>(upd_w2, 512, 512, u2hi, u2lo);

    // split h; zero agg
    fsplit_kernel<<<(NN * HH / 4 + 255) / 256, 256>>>((const float4*)h, (uint2*)hhi, (uint2*)hlo, NN * HH / 4);
    zero_kernel<<<(NN * HH / 4 + 255) / 256, 256>>>((float4*)agg, NN * HH / 4);

    // edge update -> e_new (d_out) + e hi/lo
    edge_update_kernel<<<EE / 128, 256, 17 * 1040 * 4>>>(
        h, edge_a, em_w1, em_b1, em_w2, em_b2, eg_w, eg_b, en_g, en_b,
        src, dst, e_new, ehi, elo);

    // stage 3: T = gelu([h[src] | e_new] @ msg_w1 + b1)  (Kp=576)
    mma_gemm<1><<<dim3(4, EE / 128), 256, 65536>>>(
        hhi, hlo, HH, src, 16, ehi, elo, EDD, 32,
        w1hi, w1lo, 576, msg_b1, nullptr, Thi, Tlo, nullptr, EE);

    // stage 4: agg[dst] += T @ msg_w2 + b2
    mma_gemm<2><<<dim3(4, EE / 128), 256, 65536>>>(
        Thi, Tlo, HH, nullptr, 16, Thi, Tlo, HH, 0,
        w2hi, w2lo, 512, msg_b2, agg, nullptr, nullptr, dst, EE);

    // split agg
    fsplit_kernel<<<(NN * HH / 4 + 255) / 256, 256>>>((const float4*)agg, (uint2*)ahi, (uint2*)alo, NN * HH / 4);

    // stage 5: U = gelu([h | agg] @ upd_w1 + b1)  (Kp=1024)
    mma_gemm<1><<<dim3(4, (NN + 127) / 128), 256, 65536>>>(
        hhi, hlo, HH, nullptr, 16, ahi, alo, HH, 1024,
        u1hi, u1lo, 1024, upd_b1, nullptr, Uhi, Ulo, nullptr, NN);

    // stage 6: h2 = U @ upd_w2 + b2
    mma_gemm<0><<<dim3(4, (NN + 127) / 128), 256, 65536>>>(
        Uhi, Ulo, HH, nullptr, 16, Uhi, Ulo, HH, 0,
        u2hi, u2lo, 512, upd_b2, h2, nullptr, nullptr, nullptr, NN);

    // h_out = LN(h + h2)
    node_out_kernel<<<NN, 128>>>(h, h2, norm_g, norm_b, h_out);
}

// round 11
// speedup vs baseline: 2.0382x; 1.1859x over previous
#include <cuda_runtime.h>
#include <cuda_fp16.h>
#include <math.h>
#include <stdint.h>

#define NN 10000
#define EE 160000
#define HH 512
#define EDD 16
#define LNEPS 1e-5f
#define EDGE_SCALE 0.1f

// ---------------- scratch (no allocations allowed) ----------------
__device__ __half g_Thi[(size_t)EE * HH];
__device__ __half g_Tlo[(size_t)EE * HH];
__device__ float  g_agg[(size_t)NN * HH];
__device__ __half g_Uhi[(size_t)NN * HH];
__device__ __half g_Ulo[(size_t)NN * HH];
__device__ float  g_h2[(size_t)NN * HH];
__device__ __half g_hhi[(size_t)NN * HH];
__device__ __half g_hlo[(size_t)NN * HH];
__device__ __half g_ahi[(size_t)NN * HH];
__device__ __half g_alo[(size_t)NN * HH];
__device__ __half g_ehi[(size_t)EE * EDD];
__device__ __half g_elo[(size_t)EE * EDD];
// transposed + split weights: [512][Kp] fp16 (n-major, k contiguous)
__device__ __half g_w1hi[512 * 576],  g_w1lo[512 * 576];   // msg_w1 (K=528,Kp=576)
__device__ __half g_w2hi[512 * 512],  g_w2lo[512 * 512];   // msg_w2
__device__ __half g_u1hi[512 * 1024], g_u1lo[512 * 1024];  // upd_w1
__device__ __half g_u2hi[512 * 512],  g_u2lo[512 * 512];   // upd_w2

__device__ __forceinline__ float gelu_exact(float x) {
    return 0.5f * x * (1.0f + erff(x * 0.70710678118654752440f));
}

__device__ __forceinline__ uint32_t smem_u32(const void* p) {
    uint32_t a;
    asm("{ .reg .u64 t; cvta.to.shared.u64 t, %1; cvt.u32.u64 %0, t; }" : "=r"(a) : "l"(p));
    return a;
}

// swizzle: XOR bits[4:5] with bits[7:8] -> conflict-free 16B ldmatrix/STS on 64B rows
__device__ __forceinline__ uint32_t sw64(uint32_t x) {
    return x ^ (((x >> 7) & 3u) << 4);
}

__device__ __forceinline__ uint32_t pack_half(float a, float b) {
    __half2 p = __floats2half2_rn(a, b);
    return *reinterpret_cast<uint32_t*>(&p);
}
__device__ __forceinline__ float hi_half(float x) {
    return __half2float(__float2half_rn(x));
}

#define LDMATRIX_X4(r0, r1, r2, r3, addr) \
    asm volatile("ldmatrix.sync.aligned.m8n8.x4.shared.b16 {%0,%1,%2,%3}, [%4];" \
                 : "=r"(r0), "=r"(r1), "=r"(r2), "=r"(r3) : "r"(addr))

__device__ __forceinline__ void mma_fp16(float& d0, float& d1, float& d2, float& d3,
                                         uint32_t a0, uint32_t a1, uint32_t a2, uint32_t a3,
                                         uint32_t b0, uint32_t b1) {
    asm volatile(
        "mma.sync.aligned.m16n8k16.row.col.f32.f16.f16.f32 "
        "{%0,%1,%2,%3}, {%4,%5,%6,%7}, {%8,%9}, {%0,%1,%2,%3};"
        : "+f"(d0), "+f"(d1), "+f"(d2), "+f"(d3)
        : "r"(a0), "r"(a1), "r"(a2), "r"(a3), "r"(b0), "r"(b1));
}

__device__ __forceinline__ void cp16(uint32_t dst, const void* src, uint32_t ss) {
    asm volatile("cp.async.cg.shared.global [%0], [%1], 16, %2;"
                 :: "r"(dst), "l"(src), "r"(ss) : "memory");
}
#define CP_COMMIT() asm volatile("cp.async.commit_group;" ::: "memory")
#define CP_WAIT(n)  asm volatile("cp.async.wait_group %0;" :: "n"(n) : "memory")

// ---------------- weight transpose + fp16 hi/lo split ----------------
__global__ void wsplit_kernel(const float* __restrict__ W, int K, int Kp,
                              __half* __restrict__ ohi, __half* __restrict__ olo) {
    __shared__ float t[32][33];
    int kb = blockIdx.x * 32, nb = blockIdx.y * 32;
    int tx = threadIdx.x, ty = threadIdx.y;  // 32 x 8
#pragma unroll
    for (int r = 0; r < 4; r++) {
        int k = kb + ty + r * 8;
        t[ty + r * 8][tx] = (k < K) ? W[(size_t)k * 512 + nb + tx] : 0.0f;
    }
    __syncthreads();
#pragma unroll
    for (int r = 0; r < 4; r++) {
        int n = nb + ty + r * 8;
        int k = kb + tx;
        float v = t[tx][ty + r * 8];
        __half h = __float2half_rn(v);
        ohi[(size_t)n * Kp + k] = h;
        olo[(size_t)n * Kp + k] = __float2half_rn(v - __half2float(h));
    }
}

// ---------------- fp32 -> fp16 hi/lo elementwise split ----------------
__global__ void fsplit_kernel(const float4* __restrict__ in,
                              uint2* __restrict__ oh, uint2* __restrict__ ol, int n4) {
    int i = blockIdx.x * blockDim.x + threadIdx.x;
    if (i >= n4) return;
    float4 f = in[i];
    oh[i] = make_uint2(pack_half(f.x, f.y), pack_half(f.z, f.w));
    ol[i] = make_uint2(pack_half(f.x - hi_half(f.x), f.y - hi_half(f.y)),
                       pack_half(f.z - hi_half(f.z), f.w - hi_half(f.w)));
}

// ---------------- zero ----------------
__global__ void zero_kernel(float4* __restrict__ p, int n4) {
    int i = blockIdx.x * blockDim.x + threadIdx.x;
    if (i < n4) p[i] = make_float4(0.f, 0.f, 0.f, 0.f);
}

// ---------------- HMMA GEMM, cp.async double-buffered, fp16 multi-pass ----------------
// C[M x 512]; CTA tile 128m x 128n; BK=32.
// PASSES 2: D = Ah*Bh + Al*Bh   (B single fp16; err ~2^-12)
// PASSES 3: D += Ah*Bl          (err ~2^-22)
// A rows: k < 32*C1 from a1 (rowmap gather, stride s1); then a2 (identity rows,
// stride s2 elems, tb2 valid bytes); zeros beyond.
// EPI 0: fp32 store (+bias); EPI 1: gelu -> fp16 hi/lo; EPI 2: red.add scatter (+bias).
template <int PASSES, int EPI>
__global__ __launch_bounds__(256) void mma_gemm(
    const __half* __restrict__ a1h, const __half* __restrict__ a1l,
    int s1, const int* __restrict__ map1, int C1,
    const __half* __restrict__ a2h, const __half* __restrict__ a2l,
    int s2, int tb2,
    const __half* __restrict__ bh, const __half* __restrict__ bl, int Kp,
    const float* __restrict__ bias,
    float* __restrict__ outf,
    __half* __restrict__ out_hi, __half* __restrict__ out_lo,
    const int* __restrict__ scatter, int M)
{
    extern __shared__ __align__(16) char smem[];
    constexpr int AHI = 0, ALO = 8192, BHI = 16384, BLO = 24576;
    constexpr int BUF = (PASSES == 3) ? 32768 : 24576;

    const int tid = threadIdx.x;
    const int wid = tid >> 5, lid = tid & 31;
    const int m0 = blockIdx.y * 128;
    const int n0 = blockIdx.x * 128;
    const int wm = wid & 3;
    const int wn = wid >> 2;
    const int NC = Kp / 32;
    const uint32_t sb = smem_u32(smem);

    // loader mapping: 2 threads per row
    const int lrow = tid >> 1;
    const int lh32 = (tid & 1) * 32;
    const int grA = m0 + lrow;
    const bool rowok = (grA < M);
    int r1 = 0;
    if (rowok) r1 = map1 ? map1[grA] : grA;
    const char* a1hp = (const char*)(a1h + (size_t)r1 * s1);
    const char* a1lp = (const char*)(a1l + (size_t)r1 * s1);
    const char* a2hp = (const char*)(a2h + (size_t)grA * (rowok ? s2 : 0));
    const char* a2lp = (const char*)(a2l + (size_t)grA * (rowok ? s2 : 0));
    const char* bhp = (const char*)(bh + (size_t)(n0 + lrow) * Kp);
    const char* blp = (const char*)(bl + (size_t)(n0 + lrow) * Kp);

    const uint32_t dA0 = sw64((uint32_t)(lrow * 64 + lh32));
    const uint32_t dA1 = sw64((uint32_t)(lrow * 64 + lh32 + 16));

    auto load_chunk = [&](int c, int bufi) {
        uint32_t base = sb + bufi * BUF;
        const char *sh, *sl;
        int valid;
        if (c < C1) {
            sh = a1hp + c * 64; sl = a1lp + c * 64;
            valid = rowok ? 64 : 0;
        } else {
            int off = (c - C1) * 64;
            sh = a2hp + off; sl = a2lp + off;
            int v = tb2 - off;
            v = v < 0 ? 0 : (v > 64 ? 64 : v);
            valid = rowok ? v : 0;
        }
        int ss0 = valid - lh32;      ss0 = ss0 < 0 ? 0 : (ss0 > 16 ? 16 : ss0);
        int ss1 = valid - lh32 - 16; ss1 = ss1 < 0 ? 0 : (ss1 > 16 ? 16 : ss1);
        cp16(base + AHI + dA0, sh + lh32,      (uint32_t)ss0);
        cp16(base + AHI + dA1, sh + lh32 + 16, (uint32_t)ss1);
        cp16(base + ALO + dA0, sl + lh32,      (uint32_t)ss0);
        cp16(base + ALO + dA1, sl + lh32 + 16, (uint32_t)ss1);
        const char* bsh = bhp + c * 64;
        cp16(base + BHI + dA0, bsh + lh32,      16u);
        cp16(base + BHI + dA1, bsh + lh32 + 16, 16u);
        if (PASSES == 3) {
            const char* bsl = blp + c * 64;
            cp16(base + BLO + dA0, bsl + lh32,      16u);
            cp16(base + BLO + dA1, bsl + lh32 + 16, 16u);
        }
    };

    float acc[2][8][4];
#pragma unroll
    for (int i = 0; i < 2; i++)
#pragma unroll
        for (int j = 0; j < 8; j++)
#pragma unroll
            for (int q = 0; q < 4; q++) acc[i][j][q] = 0.0f;

    // ldmatrix offsets
    const int fr = lid & 15;
    const uint32_t a_col = (uint32_t)((lid >> 4) * 16);
    uint32_t a_soff[2];
#pragma unroll
    for (int mi = 0; mi < 2; mi++)
        a_soff[mi] = (uint32_t)((wm * 32 + mi * 16 + fr) * 64) + a_col;
    const uint32_t b_base = (uint32_t)((wn * 64 + (lid & 7) + ((lid >> 4) & 1) * 8) * 64 +
                                       (((lid >> 3) & 1) * 16));

    load_chunk(0, 0);
    CP_COMMIT();

    for (int c = 0; c < NC; c++) {
        if (c + 1 < NC) { load_chunk(c + 1, (c + 1) & 1); CP_COMMIT(); CP_WAIT(1); }
        else           { CP_WAIT(0); }
        __syncthreads();
        uint32_t bufb = sb + (c & 1) * BUF;

#pragma unroll
        for (int kk = 0; kk < 2; kk++) {
            uint32_t ah[2][4], al[2][4];
#pragma unroll
            for (int mi = 0; mi < 2; mi++) {
                uint32_t so = sw64(a_soff[mi] + (uint32_t)(kk * 32));
                LDMATRIX_X4(ah[mi][0], ah[mi][1], ah[mi][2], ah[mi][3], bufb + AHI + so);
                LDMATRIX_X4(al[mi][0], al[mi][1], al[mi][2], al[mi][3], bufb + ALO + so);
            }
#pragma unroll
            for (int ni = 0; ni < 8; ni += 2) {
                uint32_t so = sw64(b_base + (uint32_t)(ni * 8 * 64) + (uint32_t)(kk * 32));
                uint32_t bh0, bh1, bh2, bh3;
                LDMATRIX_X4(bh0, bh1, bh2, bh3, bufb + BHI + so);
                uint32_t bl0, bl1, bl2, bl3;
                if (PASSES == 3) LDMATRIX_X4(bl0, bl1, bl2, bl3, bufb + BLO + so);
#pragma unroll
                for (int mi = 0; mi < 2; mi++) {
                    float* d = acc[mi][ni];
                    mma_fp16(d[0], d[1], d[2], d[3],
                             ah[mi][0], ah[mi][1], ah[mi][2], ah[mi][3], bh0, bh1);
                    mma_fp16(d[0], d[1], d[2], d[3],
                             al[mi][0], al[mi][1], al[mi][2], al[mi][3], bh0, bh1);
                    if (PASSES == 3)
                        mma_fp16(d[0], d[1], d[2], d[3],
                                 ah[mi][0], ah[mi][1], ah[mi][2], ah[mi][3], bl0, bl1);
                    float* e = acc[mi][ni + 1];
                    mma_fp16(e[0], e[1], e[2], e[3],
                             ah[mi][0], ah[mi][1], ah[mi][2], ah[mi][3], bh2, bh3);
                    mma_fp16(e[0], e[1], e[2], e[3],
                             al[mi][0], al[mi][1], al[mi][2], al[mi][3], bh2, bh3);
                    if (PASSES == 3)
                        mma_fp16(e[0], e[1], e[2], e[3],
                                 ah[mi][0], ah[mi][1], ah[mi][2], ah[mi][3], bl2, bl3);
                }
            }
        }
        __syncthreads();
    }

    // ---- epilogue ----
#pragma unroll
    for (int mi = 0; mi < 2; mi++) {
        int r0 = m0 + wm * 32 + mi * 16 + (lid >> 2);
        int r1o = r0 + 8;
        int or0 = -1, or1 = -1;
        if (EPI == 2) {
            if (r0 < M) or0 = scatter[r0];
            if (r1o < M) or1 = scatter[r1o];
        }
#pragma unroll
        for (int ni = 0; ni < 8; ni++) {
            int gc = n0 + wn * 64 + ni * 8 + (lid & 3) * 2;
            float b0 = __ldg(bias + gc), b1 = __ldg(bias + gc + 1);
            float* d = acc[mi][ni];
            if (EPI == 0) {
                if (r0 < M)
                    *reinterpret_cast<float2*>(outf + (size_t)r0 * 512 + gc) =
                        make_float2(d[0] + b0, d[1] + b1);
                if (r1o < M)
                    *reinterpret_cast<float2*>(outf + (size_t)r1o * 512 + gc) =
                        make_float2(d[2] + b0, d[3] + b1);
            } else if (EPI == 1) {
                if (r0 < M) {
                    float a = gelu_exact(d[0] + b0), b = gelu_exact(d[1] + b1);
                    *reinterpret_cast<uint32_t*>(out_hi + (size_t)r0 * 512 + gc) = pack_half(a, b);
                    *reinterpret_cast<uint32_t*>(out_lo + (size_t)r0 * 512 + gc) =
                        pack_half(a - hi_half(a), b - hi_half(b));
                }
                if (r1o < M) {
                    float a = gelu_exact(d[2] + b0), b = gelu_exact(d[3] + b1);
                    *reinterpret_cast<uint32_t*>(out_hi + (size_t)r1o * 512 + gc) = pack_half(a, b);
                    *reinterpret_cast<uint32_t*>(out_lo + (size_t)r1o * 512 + gc) =
                        pack_half(a - hi_half(a), b - hi_half(b));
                }
            } else {
                if (or0 >= 0) {
                    float* p = outf + (size_t)or0 * 512 + gc;
                    asm volatile("red.global.add.v2.f32 [%0], {%1,%2};"
                                 :: "l"(p), "f"(d[0] + b0), "f"(d[1] + b1) : "memory");
                }
                if (or1 >= 0) {
                    float* p = outf + (size_t)or1 * 512 + gc;
                    asm volatile("red.global.add.v2.f32 [%0], {%1,%2};"
                                 :: "l"(p), "f"(d[2] + b0), "f"(d[3] + b1) : "memory");
                }
            }
        }
    }
}

// ---------------- edge update: SMEM-cached weights, 2 edges per warp ----------------
__global__ __launch_bounds__(256) void edge_update_kernel(
    const float* __restrict__ h,
    const float* __restrict__ edge_attr,
    const float* __restrict__ em_w1, const float* __restrict__ em_b1,
    const float* __restrict__ em_w2, const float* __restrict__ em_b2,
    const float* __restrict__ eg_w,  const float* __restrict__ eg_b,
    const float* __restrict__ en_g,  const float* __restrict__ en_b,
    const int* __restrict__ src, const int* __restrict__ dst,
    float* __restrict__ e_new,
    __half* __restrict__ e_hi, __half* __restrict__ e_lo)
{
    extern __shared__ __align__(16) float wt[];   // 17 * 1040 floats
    const int tid = threadIdx.x;
    const int wid = tid >> 5, lane = tid & 31;

    for (int t = tid; t < 1040 * 16; t += 256) {
        int i = t >> 4, j = t & 15;
        wt[j * 1040 + i] = em_w1[t];
    }
    for (int t = tid; t < 1040; t += 256)
        wt[16 * 1040 + t] = eg_w[t];
    __syncthreads();

    const int half = lane >> 4;
    const int loc  = lane & 15;

    const int ctaBase = blockIdx.x * 128;
#pragma unroll 1
    for (int it = 0; it < 8; it++) {
        int e0 = ctaBase + wid * 16 + it * 2;
        int e1 = e0 + 1;
        const float* hs0 = h + (size_t)src[e0] * HH;
        const float* hd0 = h + (size_t)dst[e0] * HH;
        const float* hs1 = h + (size_t)src[e1] * HH;
        const float* hd1 = h + (size_t)dst[e1] * HH;

        float acc0[17], acc1[17];
#pragma unroll
        for (int j = 0; j < 17; j++) { acc0[j] = 0.0f; acc1[j] = 0.0f; }

#pragma unroll
        for (int blk = 0; blk < 8; blk++) {
            int i0 = blk * 128 + lane * 4;
            float4 z0 = (i0 < 512) ? *reinterpret_cast<const float4*>(hs0 + i0)
                                   : *reinterpret_cast<const float4*>(hd0 + i0 - 512);
            float4 z1 = (i0 < 512) ? *reinterpret_cast<const float4*>(hs1 + i0)
                                   : *reinterpret_cast<const float4*>(hd1 + i0 - 512);
#pragma unroll
            for (int j = 0; j < 17; j++) {
                float4 w = *reinterpret_cast<const float4*>(&wt[j * 1040 + i0]);
                acc0[j] += z0.x * w.x + z0.y * w.y + z0.z * w.z + z0.w * w.w;
                acc1[j] += z1.x * w.x + z1.y * w.y + z1.z * w.z + z1.w * w.w;
            }
        }
        if (lane < 4) {
            int i0 = 1024 + lane * 4;
            float4 z0 = *reinterpret_cast<const float4*>(edge_attr + (size_t)e0 * EDD + lane * 4);
            float4 z1 = *reinterpret_cast<const float4*>(edge_attr + (size_t)e1 * EDD + lane * 4);
#pragma unroll
            for (int j = 0; j < 17; j++) {
                float4 w = *reinterpret_cast<const float4*>(&wt[j * 1040 + i0]);
                acc0[j] += z0.x * w.x + z0.y * w.y + z0.z * w.z + z0.w * w.w;
                acc1[j] += z1.x * w.x + z1.y * w.y + z1.z * w.z + z1.w * w.w;
            }
        }

#pragma unroll
        for (int j = 0; j < 17; j++) {
#pragma unroll
            for (int o = 16; o > 0; o >>= 1) {
                acc0[j] += __shfl_xor_sync(0xffffffffu, acc0[j], o);
                acc1[j] += __shfl_xor_sync(0xffffffffu, acc1[j], o);
            }
        }

        int e = half ? e1 : e0;
        float a16 = half ? acc1[16] : acc0[16];
        float aj  = half ? acc1[loc] : acc0[loc];
        float gate = 1.0f / (1.0f + expf(-(a16 + eg_b[0])));
        float gv = gelu_exact(aj + em_b1[loc]);

        float delta = em_b2[loc];
#pragma unroll
        for (int k = 0; k < 16; k++) {
            float gk = __shfl_sync(0xffffffffu, gv, k + (half << 4));
            delta += gk * em_w2[k * 16 + loc];
        }

        float x = edge_attr[(size_t)e * EDD + loc] + EDGE_SCALE * gate * delta;

        float s = x;
#pragma unroll
        for (int o = 8; o > 0; o >>= 1) s += __shfl_xor_sync(0xffffffffu, s, o);
        float mu = s * (1.0f / 16.0f);
        float d = x - mu;
        float v = d * d;
#pragma unroll
        for (int o = 8; o > 0; o >>= 1) v += __shfl_xor_sync(0xffffffffu, v, o);
        float r = rsqrtf(v * (1.0f / 16.0f) + LNEPS);
        float val = d * r * en_g[loc] + en_b[loc];
        e_new[(size_t)e * EDD + loc] = val;
        __half vh = __float2half_rn(val);
        e_hi[(size_t)e * EDD + loc] = vh;
        e_lo[(size_t)e * EDD + loc] = __float2half_rn(val - __half2float(vh));
    }
}

// ---------------- residual + LayerNorm over 512 ----------------
__global__ __launch_bounds__(128) void node_out_kernel(
    const float* __restrict__ h, const float* __restrict__ h2,
    const float* __restrict__ g, const float* __restrict__ b,
    float* __restrict__ out)
{
    int n = blockIdx.x;
    int t = threadIdx.x;
    const float* hr  = h  + (size_t)n * HH;
    const float* h2r = h2 + (size_t)n * HH;

    float x[4];
    float s = 0.0f;
#pragma unroll
    for (int i = 0; i < 4; i++) {
        int c = t + 128 * i;
        x[i] = hr[c] + h2r[c];
        s += x[i];
    }
    __shared__ float red[4];
#pragma unroll
    for (int o = 16; o > 0; o >>= 1) s += __shfl_xor_sync(0xffffffffu, s, o);
    int warp = t >> 5, lane = t & 31;
    if (lane == 0) red[warp] = s;
    __syncthreads();
    float mu = (red[0] + red[1] + red[2] + red[3]) * (1.0f / 512.0f);

    float v = 0.0f;
#pragma unroll
    for (int i = 0; i < 4; i++) { float d = x[i] - mu; v += d * d; }
#pragma unroll
    for (int o = 16; o > 0; o >>= 1) v += __shfl_xor_sync(0xffffffffu, v, o);
    __syncthreads();
    if (lane == 0) red[warp] = v;
    __syncthreads();
    float var = (red[0] + red[1] + red[2] + red[3]) * (1.0f / 512.0f);
    float r = rsqrtf(var + LNEPS);

#pragma unroll
    for (int i = 0; i < 4; i++) {
        int c = t + 128 * i;
        out[(size_t)n * HH + c] = (x[i] - mu) * r * g[c] + b[c];
    }
}

// ---------------- launch ----------------
extern "C" void kernel_launch(void* const* d_in, const int* in_sizes, int n_in,
                              void* d_out, int out_size)
{
    const float* h       = (const float*)d_in[0];
    const float* edge_a  = (const float*)d_in[1];
    const float* msg_w1  = (const float*)d_in[2];
    const float* msg_b1  = (const float*)d_in[3];
    const float* msg_w2  = (const float*)d_in[4];
    const float* msg_b2  = (const float*)d_in[5];
    const float* upd_w1  = (const float*)d_in[6];
    const float* upd_b1  = (const float*)d_in[7];
    const float* upd_w2  = (const float*)d_in[8];
    const float* upd_b2  = (const float*)d_in[9];
    const float* norm_g  = (const float*)d_in[10];
    const float* norm_b  = (const float*)d_in[11];
    const float* em_w1   = (const float*)d_in[12];
    const float* em_b1   = (const float*)d_in[13];
    const float* em_w2   = (const float*)d_in[14];
    const float* em_b2   = (const float*)d_in[15];
    const float* eg_w    = (const float*)d_in[16];
    const float* eg_b    = (const float*)d_in[17];
    const float* en_g    = (const float*)d_in[18];
    const float* en_b    = (const float*)d_in[19];
    const int*   eindex  = (const int*)d_in[20];
    const int*   src = eindex;
    const int*   dst = eindex + EE;

    float* h_out = (float*)d_out;
    float* e_new = (float*)d_out + (size_t)NN * HH;

    __half *Thi, *Tlo, *Uhi, *Ulo, *hhi, *hlo, *ahi, *alo, *ehi, *elo;
    __half *w1hi, *w1lo, *w2hi, *w2lo, *u1hi, *u1lo, *u2hi, *u2lo;
    float *agg, *h2;
    cudaGetSymbolAddress((void**)&Thi, g_Thi);  cudaGetSymbolAddress((void**)&Tlo, g_Tlo);
    cudaGetSymbolAddress((void**)&Uhi, g_Uhi);  cudaGetSymbolAddress((void**)&Ulo, g_Ulo);
    cudaGetSymbolAddress((void**)&agg, g_agg);  cudaGetSymbolAddress((void**)&h2,  g_h2);
    cudaGetSymbolAddress((void**)&hhi, g_hhi);  cudaGetSymbolAddress((void**)&hlo, g_hlo);
    cudaGetSymbolAddress((void**)&ahi, g_ahi);  cudaGetSymbolAddress((void**)&alo, g_alo);
    cudaGetSymbolAddress((void**)&ehi, g_ehi);  cudaGetSymbolAddress((void**)&elo, g_elo);
    cudaGetSymbolAddress((void**)&w1hi, g_w1hi); cudaGetSymbolAddress((void**)&w1lo, g_w1lo);
    cudaGetSymbolAddress((void**)&w2hi, g_w2hi); cudaGetSymbolAddress((void**)&w2lo, g_w2lo);
    cudaGetSymbolAddress((void**)&u1hi, g_u1hi); cudaGetSymbolAddress((void**)&u1lo, g_u1lo);
    cudaGetSymbolAddress((void**)&u2hi, g_u2hi); cudaGetSymbolAddress((void**)&u2lo, g_u2lo);

    cudaFuncSetAttribute(mma_gemm<2, 1>, cudaFuncAttributeMaxDynamicSharedMemorySize, 49152);
    cudaFuncSetAttribute(mma_gemm<2, 2>, cudaFuncAttributeMaxDynamicSharedMemorySize, 49152);
    cudaFuncSetAttribute(mma_gemm<3, 1>, cudaFuncAttributeMaxDynamicSharedMemorySize, 65536);
    cudaFuncSetAttribute(mma_gemm<3, 0>, cudaFuncAttributeMaxDynamicSharedMemorySize, 65536);
    cudaFuncSetAttribute(edge_update_kernel, cudaFuncAttributeMaxDynamicSharedMemorySize, 72000);

    // weight prep
    dim3 wb(32, 8);
    wsplit_kernel<<<dim3(576 / 32, 16), wb>>>(msg_w1, 528, 576, w1hi, w1lo);
    wsplit_kernel<<<dim3(512 / 32, 16), wb>>>(msg_w2, 512, 512, w2hi, w2lo);
    wsplit_kernel<<<dim3(1024 / 32, 16), wb>>>(upd_w1, 1024, 1024, u1hi, u1lo);
    wsplit_kernel<<<dim3(512 / 32, 16), wb>>>(upd_w2, 512, 512, u2hi, u2lo);

    // split h; zero agg
    fsplit_kernel<<<(NN * HH / 4 + 255) / 256, 256>>>((const float4*)h, (uint2*)hhi, (uint2*)hlo, NN * HH / 4);
    zero_kernel<<<(NN * HH / 4 + 255) / 256, 256>>>((float4*)agg, NN * HH / 4);

    // edge update -> e_new (d_out) + e hi/lo
    edge_update_kernel<<<EE / 128, 256, 17 * 1040 * 4>>>(
        h, edge_a, em_w1, em_b1, em_w2, em_b2, eg_w, eg_b, en_g, en_b,
        src, dst, e_new, ehi, elo);

    // stage 3 (2-pass): T = gelu([h[src] | e_new] @ msg_w1 + b1)  (Kp=576)
    mma_gemm<2, 1><<<dim3(4, EE / 128), 256, 49152>>>(
        hhi, hlo, HH, src, 16, ehi, elo, EDD, 32,
        w1hi, nullptr, 576, msg_b1, nullptr, Thi, Tlo, nullptr, EE);

    // stage 4 (2-pass): agg[dst] += T @ msg_w2 + b2
    mma_gemm<2, 2><<<dim3(4, EE / 128), 256, 49152>>>(
        Thi, Tlo, HH, nullptr, 16, Thi, Tlo, HH, 0,
        w2hi, nullptr, 512, msg_b2, agg, nullptr, nullptr, dst, EE);

    // split agg
    fsplit_kernel<<<(NN * HH / 4 + 255) / 256, 256>>>((const float4*)agg, (uint2*)ahi, (uint2*)alo, NN * HH / 4);

    // stage 5 (3-pass): U = gelu([h | agg] @ upd_w1 + b1)  (Kp=1024)
    mma_gemm<3, 1><<<dim3(4, (NN + 127) / 128), 256, 65536>>>(
        hhi, hlo, HH, nullptr, 16, ahi, alo, HH, 1024,
        u1hi, u1lo, 1024, upd_b1, nullptr, Uhi, Ulo, nullptr, NN);

    // stage 6 (3-pass): h2 = U @ upd_w2 + b2
    mma_gemm<3, 0><<<dim3(4, (NN + 127) / 128), 256, 65536>>>(
        Uhi, Ulo, HH, nullptr, 16, Uhi, Ulo, HH, 0,
        u2hi, u2lo, 512, upd_b2, h2, nullptr, nullptr, nullptr, NN);

    // h_out = LN(h + h2)
    node_out_kernel<<<NN, 128>>>(h, h2, norm_g, norm_b, h_out);
}

// round 12
// speedup vs baseline: 2.2965x; 1.1267x over previous
#include <cuda_runtime.h>
#include <cuda_fp16.h>
#include <math.h>
#include <stdint.h>

#define NN 10000
#define EE 160000
#define HH 512
#define EDD 16
#define LNEPS 1e-5f
#define EDGE_SCALE 0.1f

// ---------------- scratch (no allocations allowed) ----------------
__device__ float  g_agg[(size_t)NN * HH];    // aggT = scatter-sum of gelu(stage3)
__device__ __half g_t1hi[(size_t)NN * HH];   // aggT hi/lo (stage-4 A)
__device__ __half g_t1lo[(size_t)NN * HH];
__device__ __half g_ahi[(size_t)NN * HH];    // final agg hi/lo (stage-5 A2)
__device__ __half g_alo[(size_t)NN * HH];
__device__ __half g_Uhi[(size_t)NN * HH];
__device__ __half g_Ulo[(size_t)NN * HH];
__device__ float  g_h2[(size_t)NN * HH];
__device__ __half g_hhi[(size_t)NN * HH];
__device__ __half g_hlo[(size_t)NN * HH];
__device__ __half g_ehi[(size_t)EE * EDD];
__device__ __half g_elo[(size_t)EE * EDD];
__device__ float  g_cnt[NN];
// transposed + split weights: [512][Kp] fp16 (n-major, k contiguous)
__device__ __half g_w1hi[512 * 576],  g_w1lo[512 * 576];   // msg_w1 (K=528,Kp=576)
__device__ __half g_w2hi[512 * 512],  g_w2lo[512 * 512];   // msg_w2
__device__ __half g_u1hi[512 * 1024], g_u1lo[512 * 1024];  // upd_w1
__device__ __half g_u2hi[512 * 512],  g_u2lo[512 * 512];   // upd_w2

__device__ __forceinline__ float gelu_exact(float x) {
    return 0.5f * x * (1.0f + erff(x * 0.70710678118654752440f));
}

__device__ __forceinline__ uint32_t smem_u32(const void* p) {
    uint32_t a;
    asm("{ .reg .u64 t; cvta.to.shared.u64 t, %1; cvt.u32.u64 %0, t; }" : "=r"(a) : "l"(p));
    return a;
}

// swizzle: XOR bits[4:5] with bits[7:8] -> conflict-free 16B ldmatrix/STS on 64B rows
__device__ __forceinline__ uint32_t sw64(uint32_t x) {
    return x ^ (((x >> 7) & 3u) << 4);
}

__device__ __forceinline__ uint32_t pack_half(float a, float b) {
    __half2 p = __floats2half2_rn(a, b);
    return *reinterpret_cast<uint32_t*>(&p);
}
__device__ __forceinline__ float hi_half(float x) {
    return __half2float(__float2half_rn(x));
}

#define LDMATRIX_X4(r0, r1, r2, r3, addr) \
    asm volatile("ldmatrix.sync.aligned.m8n8.x4.shared.b16 {%0,%1,%2,%3}, [%4];" \
                 : "=r"(r0), "=r"(r1), "=r"(r2), "=r"(r3) : "r"(addr))

__device__ __forceinline__ void mma_fp16(float& d0, float& d1, float& d2, float& d3,
                                         uint32_t a0, uint32_t a1, uint32_t a2, uint32_t a3,
                                         uint32_t b0, uint32_t b1) {
    asm volatile(
        "mma.sync.aligned.m16n8k16.row.col.f32.f16.f16.f32 "
        "{%0,%1,%2,%3}, {%4,%5,%6,%7}, {%8,%9}, {%0,%1,%2,%3};"
        : "+f"(d0), "+f"(d1), "+f"(d2), "+f"(d3)
        : "r"(a0), "r"(a1), "r"(a2), "r"(a3), "r"(b0), "r"(b1));
}

__device__ __forceinline__ void cp16(uint32_t dst, const void* src, uint32_t ss) {
    asm volatile("cp.async.cg.shared.global [%0], [%1], 16, %2;"
                 :: "r"(dst), "l"(src), "r"(ss) : "memory");
}
#define CP_COMMIT() asm volatile("cp.async.commit_group;" ::: "memory")
#define CP_WAIT(n)  asm volatile("cp.async.wait_group %0;" :: "n"(n) : "memory")

// ---------------- weight transpose + fp16 hi/lo split ----------------
__global__ void wsplit_kernel(const float* __restrict__ W, int K, int Kp,
                              __half* __restrict__ ohi, __half* __restrict__ olo) {
    __shared__ float t[32][33];
    int kb = blockIdx.x * 32, nb = blockIdx.y * 32;
    int tx = threadIdx.x, ty = threadIdx.y;  // 32 x 8
#pragma unroll
    for (int r = 0; r < 4; r++) {
        int k = kb + ty + r * 8;
        t[ty + r * 8][tx] = (k < K) ? W[(size_t)k * 512 + nb + tx] : 0.0f;
    }
    __syncthreads();
#pragma unroll
    for (int r = 0; r < 4; r++) {
        int n = nb + ty + r * 8;
        int k = kb + tx;
        float v = t[tx][ty + r * 8];
        __half h = __float2half_rn(v);
        ohi[(size_t)n * Kp + k] = h;
        olo[(size_t)n * Kp + k] = __float2half_rn(v - __half2float(h));
    }
}

// ---------------- fp32 -> fp16 hi/lo elementwise split ----------------
__global__ void fsplit_kernel(const float4* __restrict__ in,
                              uint2* __restrict__ oh, uint2* __restrict__ ol, int n4) {
    int i = blockIdx.x * blockDim.x + threadIdx.x;
    if (i >= n4) return;
    float4 f = in[i];
    oh[i] = make_uint2(pack_half(f.x, f.y), pack_half(f.z, f.w));
    ol[i] = make_uint2(pack_half(f.x - hi_half(f.x), f.y - hi_half(f.y)),
                       pack_half(f.z - hi_half(f.z), f.w - hi_half(f.w)));
}

// ---------------- zero ----------------
__global__ void zero_kernel(float4* __restrict__ p, int n4) {
    int i = blockIdx.x * blockDim.x + threadIdx.x;
    if (i < n4) p[i] = make_float4(0.f, 0.f, 0.f, 0.f);
}

// ---------------- edge-count histogram ----------------
__global__ void count_kernel(const int* __restrict__ dst, float* __restrict__ cnt) {
    int e = blockIdx.x * blockDim.x + threadIdx.x;
    if (e < EE) atomicAdd(&cnt[dst[e]], 1.0f);
}

// ---------------- HMMA GEMM, cp.async double-buffered, fp16 multi-pass ----------------
// C[M x 512]; CTA tile 128m x 128n; BK=32.
// PASSES 2: D = Ah*Bh + Al*Bh   (B single fp16; err ~2^-12)
// PASSES 3: D += Ah*Bl          (err ~2^-22)
// A rows: k < 32*C1 from a1 (rowmap gather, stride s1); then a2 (identity rows,
// stride s2 elems, tb2 valid bytes); zeros beyond.
// EPI 0: fp32 store (+bias)
// EPI 1: gelu -> fp16 hi/lo store (+bias)
// EPI 3: gelu -> red.add scatter (+bias)                     [stage 3]
// EPI 4: acc + cnt[row]*bias -> fp16 hi/lo store             [stage 4]
template <int PASSES, int EPI>
__global__ __launch_bounds__(256) void mma_gemm(
    const __half* __restrict__ a1h, const __half* __restrict__ a1l,
    int s1, const int* __restrict__ map1, int C1,
    const __half* __restrict__ a2h, const __half* __restrict__ a2l,
    int s2, int tb2,
    const __half* __restrict__ bh, const __half* __restrict__ bl, int Kp,
    const float* __restrict__ bias,
    float* __restrict__ outf,
    __half* __restrict__ out_hi, __half* __restrict__ out_lo,
    const int* __restrict__ scatter, const float* __restrict__ cntp, int M)
{
    extern __shared__ __align__(16) char smem[];
    constexpr int AHI = 0, ALO = 8192, BHI = 16384, BLO = 24576;
    constexpr int BUF = (PASSES == 3) ? 32768 : 24576;

    const int tid = threadIdx.x;
    const int wid = tid >> 5, lid = tid & 31;
    const int m0 = blockIdx.y * 128;
    const int n0 = blockIdx.x * 128;
    const int wm = wid & 3;
    const int wn = wid >> 2;
    const int NC = Kp / 32;
    const uint32_t sb = smem_u32(smem);

    // loader mapping: 2 threads per row
    const int lrow = tid >> 1;
    const int lh32 = (tid & 1) * 32;
    const int grA = m0 + lrow;
    const bool rowok = (grA < M);
    int r1 = 0;
    if (rowok) r1 = map1 ? map1[grA] : grA;
    const char* a1hp = (const char*)(a1h + (size_t)r1 * s1);
    const char* a1lp = (const char*)(a1l + (size_t)r1 * s1);
    const char* a2hp = (const char*)(a2h + (size_t)grA * (rowok ? s2 : 0));
    const char* a2lp = (const char*)(a2l + (size_t)grA * (rowok ? s2 : 0));
    const char* bhp = (const char*)(bh + (size_t)(n0 + lrow) * Kp);
    const char* blp = (const char*)(bl + (size_t)(n0 + lrow) * Kp);

    const uint32_t dA0 = sw64((uint32_t)(lrow * 64 + lh32));
    const uint32_t dA1 = sw64((uint32_t)(lrow * 64 + lh32 + 16));

    auto load_chunk = [&](int c, int bufi) {
        uint32_t base = sb + bufi * BUF;
        const char *sh, *sl;
        int valid;
        if (c < C1) {
            sh = a1hp + c * 64; sl = a1lp + c * 64;
            valid = rowok ? 64 : 0;
        } else {
            int off = (c - C1) * 64;
            sh = a2hp + off; sl = a2lp + off;
            int v = tb2 - off;
            v = v < 0 ? 0 : (v > 64 ? 64 : v);
            valid = rowok ? v : 0;
        }
        int ss0 = valid - lh32;      ss0 = ss0 < 0 ? 0 : (ss0 > 16 ? 16 : ss0);
        int ss1 = valid - lh32 - 16; ss1 = ss1 < 0 ? 0 : (ss1 > 16 ? 16 : ss1);
        cp16(base + AHI + dA0, sh + lh32,      (uint32_t)ss0);
        cp16(base + AHI + dA1, sh + lh32 + 16, (uint32_t)ss1);
        cp16(base + ALO + dA0, sl + lh32,      (uint32_t)ss0);
        cp16(base + ALO + dA1, sl + lh32 + 16, (uint32_t)ss1);
        const char* bsh = bhp + c * 64;
        cp16(base + BHI + dA0, bsh + lh32,      16u);
        cp16(base + BHI + dA1, bsh + lh32 + 16, 16u);
        if (PASSES == 3) {
            const char* bsl = blp + c * 64;
            cp16(base + BLO + dA0, bsl + lh32,      16u);
            cp16(base + BLO + dA1, bsl + lh32 + 16, 16u);
        }
    };

    float acc[2][8][4];
#pragma unroll
    for (int i = 0; i < 2; i++)
#pragma unroll
        for (int j = 0; j < 8; j++)
#pragma unroll
            for (int q = 0; q < 4; q++) acc[i][j][q] = 0.0f;

    // ldmatrix offsets
    const int fr = lid & 15;
    const uint32_t a_col = (uint32_t)((lid >> 4) * 16);
    uint32_t a_soff[2];
#pragma unroll
    for (int mi = 0; mi < 2; mi++)
        a_soff[mi] = (uint32_t)((wm * 32 + mi * 16 + fr) * 64) + a_col;
    const uint32_t b_base = (uint32_t)((wn * 64 + (lid & 7) + ((lid >> 4) & 1) * 8) * 64 +
                                       (((lid >> 3) & 1) * 16));

    load_chunk(0, 0);
    CP_COMMIT();

    for (int c = 0; c < NC; c++) {
        if (c + 1 < NC) { load_chunk(c + 1, (c + 1) & 1); CP_COMMIT(); CP_WAIT(1); }
        else           { CP_WAIT(0); }
        __syncthreads();
        uint32_t bufb = sb + (c & 1) * BUF;

#pragma unroll
        for (int kk = 0; kk < 2; kk++) {
            uint32_t ah[2][4], al[2][4];
#pragma unroll
            for (int mi = 0; mi < 2; mi++) {
                uint32_t so = sw64(a_soff[mi] + (uint32_t)(kk * 32));
                LDMATRIX_X4(ah[mi][0], ah[mi][1], ah[mi][2], ah[mi][3], bufb + AHI + so);
                LDMATRIX_X4(al[mi][0], al[mi][1], al[mi][2], al[mi][3], bufb + ALO + so);
            }
#pragma unroll
            for (int ni = 0; ni < 8; ni += 2) {
                uint32_t so = sw64(b_base + (uint32_t)(ni * 8 * 64) + (uint32_t)(kk * 32));
                uint32_t bh0, bh1, bh2, bh3;
                LDMATRIX_X4(bh0, bh1, bh2, bh3, bufb + BHI + so);
                uint32_t bl0, bl1, bl2, bl3;
                if (PASSES == 3) LDMATRIX_X4(bl0, bl1, bl2, bl3, bufb + BLO + so);
#pragma unroll
                for (int mi = 0; mi < 2; mi++) {
                    float* d = acc[mi][ni];
                    mma_fp16(d[0], d[1], d[2], d[3],
                             ah[mi][0], ah[mi][1], ah[mi][2], ah[mi][3], bh0, bh1);
                    mma_fp16(d[0], d[1], d[2], d[3],
                             al[mi][0], al[mi][1], al[mi][2], al[mi][3], bh0, bh1);
                    if (PASSES == 3)
                        mma_fp16(d[0], d[1], d[2], d[3],
                                 ah[mi][0], ah[mi][1], ah[mi][2], ah[mi][3], bl0, bl1);
                    float* e = acc[mi][ni + 1];
                    mma_fp16(e[0], e[1], e[2], e[3],
                             ah[mi][0], ah[mi][1], ah[mi][2], ah[mi][3], bh2, bh3);
                    mma_fp16(e[0], e[1], e[2], e[3],
                             al[mi][0], al[mi][1], al[mi][2], al[mi][3], bh2, bh3);
                    if (PASSES == 3)
                        mma_fp16(e[0], e[1], e[2], e[3],
                                 ah[mi][0], ah[mi][1], ah[mi][2], ah[mi][3], bl2, bl3);
                }
            }
        }
        __syncthreads();
    }

    // ---- epilogue ----
#pragma unroll
    for (int mi = 0; mi < 2; mi++) {
        int r0 = m0 + wm * 32 + mi * 16 + (lid >> 2);
        int r1o = r0 + 8;
        int or0 = -1, or1 = -1;
        if (EPI == 3) {
            if (r0 < M) or0 = scatter[r0];
            if (r1o < M) or1 = scatter[r1o];
        }
        float cv0 = 0.f, cv1 = 0.f;
        if (EPI == 4) {
            if (r0 < M) cv0 = cntp[r0];
            if (r1o < M) cv1 = cntp[r1o];
        }
#pragma unroll
        for (int ni = 0; ni < 8; ni++) {
            int gc = n0 + wn * 64 + ni * 8 + (lid & 3) * 2;
            float b0 = __ldg(bias + gc), b1 = __ldg(bias + gc + 1);
            float* d = acc[mi][ni];
            if (EPI == 0) {
                if (r0 < M)
                    *reinterpret_cast<float2*>(outf + (size_t)r0 * 512 + gc) =
                        make_float2(d[0] + b0, d[1] + b1);
                if (r1o < M)
                    *reinterpret_cast<float2*>(outf + (size_t)r1o * 512 + gc) =
                        make_float2(d[2] + b0, d[3] + b1);
            } else if (EPI == 1) {
                if (r0 < M) {
                    float a = gelu_exact(d[0] + b0), b = gelu_exact(d[1] + b1);
                    *reinterpret_cast<uint32_t*>(out_hi + (size_t)r0 * 512 + gc) = pack_half(a, b);
                    *reinterpret_cast<uint32_t*>(out_lo + (size_t)r0 * 512 + gc) =
                        pack_half(a - hi_half(a), b - hi_half(b));
                }
                if (r1o < M) {
                    float a = gelu_exact(d[2] + b0), b = gelu_exact(d[3] + b1);
                    *reinterpret_cast<uint32_t*>(out_hi + (size_t)r1o * 512 + gc) = pack_half(a, b);
                    *reinterpret_cast<uint32_t*>(out_lo + (size_t)r1o * 512 + gc) =
                        pack_half(a - hi_half(a), b - hi_half(b));
                }
            } else if (EPI == 3) {
                if (or0 >= 0) {
                    float a = gelu_exact(d[0] + b0), b = gelu_exact(d[1] + b1);
                    float* p = outf + (size_t)or0 * 512 + gc;
                    asm volatile("red.global.add.v2.f32 [%0], {%1,%2};"
                                 :: "l"(p), "f"(a), "f"(b) : "memory");
                }
                if (or1 >= 0) {
                    float a = gelu_exact(d[2] + b0), b = gelu_exact(d[3] + b1);
                    float* p = outf + (size_t)or1 * 512 + gc;
                    asm volatile("red.global.add.v2.f32 [%0], {%1,%2};"
                                 :: "l"(p), "f"(a), "f"(b) : "memory");
                }
            } else {  // EPI == 4
                if (r0 < M) {
                    float a = d[0] + cv0 * b0, b = d[1] + cv0 * b1;
                    *reinterpret_cast<uint32_t*>(out_hi + (size_t)r0 * 512 + gc) = pack_half(a, b);
                    *reinterpret_cast<uint32_t*>(out_lo + (size_t)r0 * 512 + gc) =
                        pack_half(a - hi_half(a), b - hi_half(b));
                }
                if (r1o < M) {
                    float a = d[2] + cv1 * b0, b = d[3] + cv1 * b1;
                    *reinterpret_cast<uint32_t*>(out_hi + (size_t)r1o * 512 + gc) = pack_half(a, b);
                    *reinterpret_cast<uint32_t*>(out_lo + (size_t)r1o * 512 + gc) =
                        pack_half(a - hi_half(a), b - hi_half(b));
                }
            }
        }
    }
}

// ---------------- edge update: SMEM-cached weights, 2 edges per warp ----------------
__global__ __launch_bounds__(256) void edge_update_kernel(
    const float* __restrict__ h,
    const float* __restrict__ edge_attr,
    const float* __restrict__ em_w1, const float* __restrict__ em_b1,
    const float* __restrict__ em_w2, const float* __restrict__ em_b2,
    const float* __restrict__ eg_w,  const float* __restrict__ eg_b,
    const float* __restrict__ en_g,  const float* __restrict__ en_b,
    const int* __restrict__ src, const int* __restrict__ dst,
    float* __restrict__ e_new,
    __half* __restrict__ e_hi, __half* __restrict__ e_lo)
{
    extern __shared__ __align__(16) float wt[];   // 17 * 1040 floats
    const int tid = threadIdx.x;
    const int wid = tid >> 5, lane = tid & 31;

    for (int t = tid; t < 1040 * 16; t += 256) {
        int i = t >> 4, j = t & 15;
        wt[j * 1040 + i] = em_w1[t];
    }
    for (int t = tid; t < 1040; t += 256)
        wt[16 * 1040 + t] = eg_w[t];
    __syncthreads();

    const int half = lane >> 4;
    const int loc  = lane & 15;

    const int ctaBase = blockIdx.x * 128;
#pragma unroll 1
    for (int it = 0; it < 8; it++) {
        int e0 = ctaBase + wid * 16 + it * 2;
        int e1 = e0 + 1;
        const float* hs0 = h + (size_t)src[e0] * HH;
        const float* hd0 = h + (size_t)dst[e0] * HH;
        const float* hs1 = h + (size_t)src[e1] * HH;
        const float* hd1 = h + (size_t)dst[e1] * HH;

        float acc0[17], acc1[17];
#pragma unroll
        for (int j = 0; j < 17; j++) { acc0[j] = 0.0f; acc1[j] = 0.0f; }

#pragma unroll
        for (int blk = 0; blk < 8; blk++) {
            int i0 = blk * 128 + lane * 4;
            float4 z0 = (i0 < 512) ? *reinterpret_cast<const float4*>(hs0 + i0)
                                   : *reinterpret_cast<const float4*>(hd0 + i0 - 512);
            float4 z1 = (i0 < 512) ? *reinterpret_cast<const float4*>(hs1 + i0)
                                   : *reinterpret_cast<const float4*>(hd1 + i0 - 512);
#pragma unroll
            for (int j = 0; j < 17; j++) {
                float4 w = *reinterpret_cast<const float4*>(&wt[j * 1040 + i0]);
                acc0[j] += z0.x * w.x + z0.y * w.y + z0.z * w.z + z0.w * w.w;
                acc1[j] += z1.x * w.x + z1.y * w.y + z1.z * w.z + z1.w * w.w;
            }
        }
        if (lane < 4) {
            int i0 = 1024 + lane * 4;
            float4 z0 = *reinterpret_cast<const float4*>(edge_attr + (size_t)e0 * EDD + lane * 4);
            float4 z1 = *reinterpret_cast<const float4*>(edge_attr + (size_t)e1 * EDD + lane * 4);
#pragma unroll
            for (int j = 0; j < 17; j++) {
                float4 w = *reinterpret_cast<const float4*>(&wt[j * 1040 + i0]);
                acc0[j] += z0.x * w.x + z0.y * w.y + z0.z * w.z + z0.w * w.w;
                acc1[j] += z1.x * w.x + z1.y * w.y + z1.z * w.z + z1.w * w.w;
            }
        }

#pragma unroll
        for (int j = 0; j < 17; j++) {
#pragma unroll
            for (int o = 16; o > 0; o >>= 1) {
                acc0[j] += __shfl_xor_sync(0xffffffffu, acc0[j], o);
                acc1[j] += __shfl_xor_sync(0xffffffffu, acc1[j], o);
            }
        }

        int e = half ? e1 : e0;
        float a16 = half ? acc1[16] : acc0[16];
        float aj  = half ? acc1[loc] : acc0[loc];
        float gate = 1.0f / (1.0f + expf(-(a16 + eg_b[0])));
        float gv = gelu_exact(aj + em_b1[loc]);

        float delta = em_b2[loc];
#pragma unroll
        for (int k = 0; k < 16; k++) {
            float gk = __shfl_sync(0xffffffffu, gv, k + (half << 4));
            delta += gk * em_w2[k * 16 + loc];
        }

        float x = edge_attr[(size_t)e * EDD + loc] + EDGE_SCALE * gate * delta;

        float s = x;
#pragma unroll
        for (int o = 8; o > 0; o >>= 1) s += __shfl_xor_sync(0xffffffffu, s, o);
        float mu = s * (1.0f / 16.0f);
        float d = x - mu;
        float v = d * d;
#pragma unroll
        for (int o = 8; o > 0; o >>= 1) v += __shfl_xor_sync(0xffffffffu, v, o);
        float r = rsqrtf(v * (1.0f / 16.0f) + LNEPS);
        float val = d * r * en_g[loc] + en_b[loc];
        e_new[(size_t)e * EDD + loc] = val;
        __half vh = __float2half_rn(val);
        e_hi[(size_t)e * EDD + loc] = vh;
        e_lo[(size_t)e * EDD + loc] = __float2half_rn(val - __half2float(vh));
    }
}

// ---------------- residual + LayerNorm over 512 ----------------
__global__ __launch_bounds__(128) void node_out_kernel(
    const float* __restrict__ h, const float* __restrict__ h2,
    const float* __restrict__ g, const float* __restrict__ b,
    float* __restrict__ out)
{
    int n = blockIdx.x;
    int t = threadIdx.x;
    const float* hr  = h  + (size_t)n * HH;
    const float* h2r = h2 + (size_t)n * HH;

    float x[4];
    float s = 0.0f;
#pragma unroll
    for (int i = 0; i < 4; i++) {
        int c = t + 128 * i;
        x[i] = hr[c] + h2r[c];
        s += x[i];
    }
    __shared__ float red[4];
#pragma unroll
    for (int o = 16; o > 0; o >>= 1) s += __shfl_xor_sync(0xffffffffu, s, o);
    int warp = t >> 5, lane = t & 31;
    if (lane == 0) red[warp] = s;
    __syncthreads();
    float mu = (red[0] + red[1] + red[2] + red[3]) * (1.0f / 512.0f);

    float v = 0.0f;
#pragma unroll
    for (int i = 0; i < 4; i++) { float d = x[i] - mu; v += d * d; }
#pragma unroll
    for (int o = 16; o > 0; o >>= 1) v += __shfl_xor_sync(0xffffffffu, v, o);
    __syncthreads();
    if (lane == 0) red[warp] = v;
    __syncthreads();
    float var = (red[0] + red[1] + red[2] + red[3]) * (1.0f / 512.0f);
    float r = rsqrtf(var + LNEPS);

#pragma unroll
    for (int i = 0; i < 4; i++) {
        int c = t + 128 * i;
        out[(size_t)n * HH + c] = (x[i] - mu) * r * g[c] + b[c];
    }
}

// ---------------- launch ----------------
extern "C" void kernel_launch(void* const* d_in, const int* in_sizes, int n_in,
                              void* d_out, int out_size)
{
    const float* h       = (const float*)d_in[0];
    const float* edge_a  = (const float*)d_in[1];
    const float* msg_w1  = (const float*)d_in[2];
    const float* msg_b1  = (const float*)d_in[3];
    const float* msg_w2  = (const float*)d_in[4];
    const float* msg_b2  = (const float*)d_in[5];
    const float* upd_w1  = (const float*)d_in[6];
    const float* upd_b1  = (const float*)d_in[7];
    const float* upd_w2  = (const float*)d_in[8];
    const float* upd_b2  = (const float*)d_in[9];
    const float* norm_g  = (const float*)d_in[10];
    const float* norm_b  = (const float*)d_in[11];
    const float* em_w1   = (const float*)d_in[12];
    const float* em_b1   = (const float*)d_in[13];
    const float* em_w2   = (const float*)d_in[14];
    const float* em_b2   = (const float*)d_in[15];
    const float* eg_w    = (const float*)d_in[16];
    const float* eg_b    = (const float*)d_in[17];
    const float* en_g    = (const float*)d_in[18];
    const float* en_b    = (const float*)d_in[19];
    const int*   eindex  = (const int*)d_in[20];
    const int*   src = eindex;
    const int*   dst = eindex + EE;

    float* h_out = (float*)d_out;
    float* e_new = (float*)d_out + (size_t)NN * HH;

    __half *t1hi, *t1lo, *Uhi, *Ulo, *hhi, *hlo, *ahi, *alo, *ehi, *elo;
    __half *w1hi, *w1lo, *w2hi, *w2lo, *u1hi, *u1lo, *u2hi, *u2lo;
    float *agg, *h2, *cnt;
    cudaGetSymbolAddress((void**)&t1hi, g_t1hi); cudaGetSymbolAddress((void**)&t1lo, g_t1lo);
    cudaGetSymbolAddress((void**)&Uhi, g_Uhi);  cudaGetSymbolAddress((void**)&Ulo, g_Ulo);
    cudaGetSymbolAddress((void**)&agg, g_agg);  cudaGetSymbolAddress((void**)&h2,  g_h2);
    cudaGetSymbolAddress((void**)&hhi, g_hhi);  cudaGetSymbolAddress((void**)&hlo, g_hlo);
    cudaGetSymbolAddress((void**)&ahi, g_ahi);  cudaGetSymbolAddress((void**)&alo, g_alo);
    cudaGetSymbolAddress((void**)&ehi, g_ehi);  cudaGetSymbolAddress((void**)&elo, g_elo);
    cudaGetSymbolAddress((void**)&cnt, g_cnt);
    cudaGetSymbolAddress((void**)&w1hi, g_w1hi); cudaGetSymbolAddress((void**)&w1lo, g_w1lo);
    cudaGetSymbolAddress((void**)&w2hi, g_w2hi); cudaGetSymbolAddress((void**)&w2lo, g_w2lo);
    cudaGetSymbolAddress((void**)&u1hi, g_u1hi); cudaGetSymbolAddress((void**)&u1lo, g_u1lo);
    cudaGetSymbolAddress((void**)&u2hi, g_u2hi); cudaGetSymbolAddress((void**)&u2lo, g_u2lo);

    cudaFuncSetAttribute(mma_gemm<2, 3>, cudaFuncAttributeMaxDynamicSharedMemorySize, 49152);
    cudaFuncSetAttribute(mma_gemm<3, 4>, cudaFuncAttributeMaxDynamicSharedMemorySize, 65536);
    cudaFuncSetAttribute(mma_gemm<3, 1>, cudaFuncAttributeMaxDynamicSharedMemorySize, 65536);
    cudaFuncSetAttribute(mma_gemm<3, 0>, cudaFuncAttributeMaxDynamicSharedMemorySize, 65536);
    cudaFuncSetAttribute(edge_update_kernel, cudaFuncAttributeMaxDynamicSharedMemorySize, 72000);

    // weight prep
    dim3 wb(32, 8);
    wsplit_kernel<<<dim3(576 / 32, 16), wb>>>(msg_w1, 528, 576, w1hi, w1lo);
    wsplit_kernel<<<dim3(512 / 32, 16), wb>>>(msg_w2, 512, 512, w2hi, w2lo);
    wsplit_kernel<<<dim3(1024 / 32, 16), wb>>>(upd_w1, 1024, 1024, u1hi, u1lo);
    wsplit_kernel<<<dim3(512 / 32, 16), wb>>>(upd_w2, 512, 512, u2hi, u2lo);

    // split h; zero agg + cnt; count edges per node
    fsplit_kernel<<<(NN * HH / 4 + 255) / 256, 256>>>((const float4*)h, (uint2*)hhi, (uint2*)hlo, NN * HH / 4);
    zero_kernel<<<(NN * HH / 4 + 255) / 256, 256>>>((float4*)agg, NN * HH / 4);
    zero_kernel<<<(NN / 4 + 255) / 256, 256>>>((float4*)cnt, NN / 4);
    count_kernel<<<(EE + 255) / 256, 256>>>(dst, cnt);

    // edge update -> e_new (d_out) + e hi/lo
    edge_update_kernel<<<EE / 128, 256, 17 * 1040 * 4>>>(
        h, edge_a, em_w1, em_b1, em_w2, em_b2, eg_w, eg_b, en_g, en_b,
        src, dst, e_new, ehi, elo);

    // stage 3 (2-pass): aggT[dst] += gelu([h[src] | e_new] @ msg_w1 + b1)  (Kp=576)
    mma_gemm<2, 3><<<dim3(4, EE / 128), 256, 49152>>>(
        hhi, hlo, HH, src, 16, ehi, elo, EDD, 32,
        w1hi, nullptr, 576, msg_b1, agg, nullptr, nullptr, dst, nullptr, EE);

    // split aggT
    fsplit_kernel<<<(NN * HH / 4 + 255) / 256, 256>>>((const float4*)agg, (uint2*)t1hi, (uint2*)t1lo, NN * HH / 4);

    // stage 4 (3-pass, N-scale): agg = aggT @ msg_w2 + cnt*b2  -> fp16 hi/lo
    mma_gemm<3, 4><<<dim3(4, (NN + 127) / 128), 256, 65536>>>(
        t1hi, t1lo, HH, nullptr, 16, t1hi, t1lo, HH, 0,
        w2hi, w2lo, 512, msg_b2, nullptr, ahi, alo, nullptr, cnt, NN);

    // stage 5 (3-pass): U = gelu([h | agg] @ upd_w1 + b1)  (Kp=1024)
    mma_gemm<3, 1><<<dim3(4, (NN + 127) / 128), 256, 65536>>>(
        hhi, hlo, HH, nullptr, 16, ahi, alo, HH, 1024,
        u1hi, u1lo, 1024, upd_b1, nullptr, Uhi, Ulo, nullptr, nullptr, NN);

    // stage 6 (3-pass): h2 = U @ upd_w2 + b2
    mma_gemm<3, 0><<<dim3(4, (NN + 127) / 128), 256, 65536>>>(
        Uhi, Ulo, HH, nullptr, 16, Uhi, Ulo, HH, 0,
        u2hi, u2lo, 512, upd_b2, h2, nullptr, nullptr, nullptr, nullptr, NN);

    // h_out = LN(h + h2)
    node_out_kernel<<<NN, 128>>>(h, h2, norm_g, norm_b, h_out);
}

// round 14
// speedup vs baseline: 2.7667x; 1.2048x over previous
#include <cuda_runtime.h>
#include <cuda_fp16.h>
#include <math.h>
#include <stdint.h>

#define NN 10000
#define EE 160000
#define HH 512
#define EDD 16
#define LNEPS 1e-5f
#define EDGE_SCALE 0.1f

// ---------------- scratch (no allocations allowed) ----------------
__device__ float  g_P[(size_t)NN * HH];      // h @ msg_w1[:512] + b1
__device__ float  g_agg[(size_t)NN * HH];    // scatter-sum of gelu messages
__device__ __half g_t1hi[(size_t)NN * HH];   // agg hi/lo (stage-4 A)
__device__ __half g_t1lo[(size_t)NN * HH];
__device__ __half g_ahi[(size_t)NN * HH];    // msg output agg hi/lo (stage-5 A2)
__device__ __half g_alo[(size_t)NN * HH];
__device__ __half g_Uhi[(size_t)NN * HH];
__device__ __half g_Ulo[(size_t)NN * HH];
__device__ float  g_h2[(size_t)NN * HH];
__device__ __half g_hhi[(size_t)NN * HH];
__device__ __half g_hlo[(size_t)NN * HH];
__device__ float  g_cnt[NN];
// transposed + split weights: [512][Kp] fp16 (n-major, k contiguous)
__device__ __half g_w1hi[512 * 512],  g_w1lo[512 * 512];   // msg_w1 rows 0..511
__device__ __half g_w2hi[512 * 512],  g_w2lo[512 * 512];   // msg_w2
__device__ __half g_u1hi[512 * 1024], g_u1lo[512 * 1024];  // upd_w1
__device__ __half g_u2hi[512 * 512],  g_u2lo[512 * 512];   // upd_w2

__device__ __forceinline__ float gelu_exact(float x) {
    return 0.5f * x * (1.0f + erff(x * 0.70710678118654752440f));
}

__device__ __forceinline__ uint32_t smem_u32(const void* p) {
    uint32_t a;
    asm("{ .reg .u64 t; cvta.to.shared.u64 t, %1; cvt.u32.u64 %0, t; }" : "=r"(a) : "l"(p));
    return a;
}

__device__ __forceinline__ uint32_t sw64(uint32_t x) {
    return x ^ (((x >> 7) & 3u) << 4);
}

__device__ __forceinline__ uint32_t pack_half(float a, float b) {
    __half2 p = __floats2half2_rn(a, b);
    return *reinterpret_cast<uint32_t*>(&p);
}
__device__ __forceinline__ float hi_half(float x) {
    return __half2float(__float2half_rn(x));
}

#define LDMATRIX_X4(r0, r1, r2, r3, addr) \
    asm volatile("ldmatrix.sync.aligned.m8n8.x4.shared.b16 {%0,%1,%2,%3}, [%4];" \
                 : "=r"(r0), "=r"(r1), "=r"(r2), "=r"(r3) : "r"(addr))

__device__ __forceinline__ void mma_fp16(float& d0, float& d1, float& d2, float& d3,
                                         uint32_t a0, uint32_t a1, uint32_t a2, uint32_t a3,
                                         uint32_t b0, uint32_t b1) {
    asm volatile(
        "mma.sync.aligned.m16n8k16.row.col.f32.f16.f16.f32 "
        "{%0,%1,%2,%3}, {%4,%5,%6,%7}, {%8,%9}, {%0,%1,%2,%3};"
        : "+f"(d0), "+f"(d1), "+f"(d2), "+f"(d3)
        : "r"(a0), "r"(a1), "r"(a2), "r"(a3), "r"(b0), "r"(b1));
}

__device__ __forceinline__ void cp16(uint32_t dst, const void* src, uint32_t ss) {
    asm volatile("cp.async.cg.shared.global [%0], [%1], 16, %2;"
                 :: "r"(dst), "l"(src), "r"(ss) : "memory");
}
#define CP_COMMIT() asm volatile("cp.async.commit_group;" ::: "memory")
#define CP_WAIT(n)  asm volatile("cp.async.wait_group %0;" :: "n"(n) : "memory")

// ---------------- weight transpose + fp16 hi/lo split ----------------
__global__ void wsplit_kernel(const float* __restrict__ W, int K, int Kp,
                              __half* __restrict__ ohi, __half* __restrict__ olo) {
    __shared__ float t[32][33];
    int kb = blockIdx.x * 32, nb = blockIdx.y * 32;
    int tx = threadIdx.x, ty = threadIdx.y;  // 32 x 8
#pragma unroll
    for (int r = 0; r < 4; r++) {
        int k = kb + ty + r * 8;
        t[ty + r * 8][tx] = (k < K) ? W[(size_t)k * 512 + nb + tx] : 0.0f;
    }
    __syncthreads();
#pragma unroll
    for (int r = 0; r < 4; r++) {
        int n = nb + ty + r * 8;
        int k = kb + tx;
        float v = t[tx][ty + r * 8];
        __half h = __float2half_rn(v);
        ohi[(size_t)n * Kp + k] = h;
        olo[(size_t)n * Kp + k] = __float2half_rn(v - __half2float(h));
    }
}

// ---------------- fp32 -> fp16 hi/lo elementwise split ----------------
__global__ void fsplit_kernel(const float4* __restrict__ in,
                              uint2* __restrict__ oh, uint2* __restrict__ ol, int n4) {
    int i = blockIdx.x * blockDim.x + threadIdx.x;
    if (i >= n4) return;
    float4 f = in[i];
    oh[i] = make_uint2(pack_half(f.x, f.y), pack_half(f.z, f.w));
    ol[i] = make_uint2(pack_half(f.x - hi_half(f.x), f.y - hi_half(f.y)),
                       pack_half(f.z - hi_half(f.z), f.w - hi_half(f.w)));
}

// ---------------- zero ----------------
__global__ void zero_kernel(float4* __restrict__ p, int n4) {
    int i = blockIdx.x * blockDim.x + threadIdx.x;
    if (i < n4) p[i] = make_float4(0.f, 0.f, 0.f, 0.f);
}

// ---------------- edge-count histogram ----------------
__global__ void count_kernel(const int* __restrict__ dst, float* __restrict__ cnt) {
    int e = blockIdx.x * blockDim.x + threadIdx.x;
    if (e < EE) atomicAdd(&cnt[dst[e]], 1.0f);
}

// ---------------- HMMA GEMM, cp.async double-buffered, 3-pass fp16 ----------------
// C[M x 512]; CTA tile 128m x 128n; BK=32. D = Ah*Bh + Al*Bh + Ah*Bl (err ~2^-22).
// A rows: k < 32*C1 from a1 (stride s1); then a2 (stride s2, tb2 valid bytes); zeros beyond.
// EPI 0: fp32 store (+bias)
// EPI 1: gelu -> fp16 hi/lo store (+bias)
// EPI 4: acc + cnt[row]*bias -> fp16 hi/lo store
template <int EPI>
__global__ __launch_bounds__(256) void mma_gemm(
    const __half* __restrict__ a1h, const __half* __restrict__ a1l,
    int s1, int C1,
    const __half* __restrict__ a2h, const __half* __restrict__ a2l,
    int s2, int tb2,
    const __half* __restrict__ bh, const __half* __restrict__ bl, int Kp,
    const float* __restrict__ bias,
    float* __restrict__ outf,
    __half* __restrict__ out_hi, __half* __restrict__ out_lo,
    const float* __restrict__ cntp, int M)
{
    extern __shared__ __align__(16) char smem[];
    constexpr int AHI = 0, ALO = 8192, BHI = 16384, BLO = 24576, BUF = 32768;

    const int tid = threadIdx.x;
    const int wid = tid >> 5, lid = tid & 31;
    const int m0 = blockIdx.y * 128;
    const int n0 = blockIdx.x * 128;
    const int wm = wid & 3;
    const int wn = wid >> 2;
    const int NC = Kp / 32;
    const uint32_t sb = smem_u32(smem);

    const int lrow = tid >> 1;
    const int lh32 = (tid & 1) * 32;
    const int grA = m0 + lrow;
    const bool rowok = (grA < M);
    const char* a1hp = (const char*)(a1h + (size_t)(rowok ? grA : 0) * s1);
    const char* a1lp = (const char*)(a1l + (size_t)(rowok ? grA : 0) * s1);
    const char* a2hp = (const char*)(a2h + (size_t)(rowok ? grA : 0) * s2);
    const char* a2lp = (const char*)(a2l + (size_t)(rowok ? grA : 0) * s2);
    const char* bhp = (const char*)(bh + (size_t)(n0 + lrow) * Kp);
    const char* blp = (const char*)(bl + (size_t)(n0 + lrow) * Kp);

    const uint32_t dA0 = sw64((uint32_t)(lrow * 64 + lh32));
    const uint32_t dA1 = sw64((uint32_t)(lrow * 64 + lh32 + 16));

    auto load_chunk = [&](int c, int bufi) {
        uint32_t base = sb + bufi * BUF;
        const char *sh, *sl;
        int valid;
        if (c < C1) {
            sh = a1hp + c * 64; sl = a1lp + c * 64;
            valid = rowok ? 64 : 0;
        } else {
            int off = (c - C1) * 64;
            sh = a2hp + off; sl = a2lp + off;
            int v = tb2 - off;
            v = v < 0 ? 0 : (v > 64 ? 64 : v);
            valid = rowok ? v : 0;
        }
        int ss0 = valid - lh32;      ss0 = ss0 < 0 ? 0 : (ss0 > 16 ? 16 : ss0);
        int ss1 = valid - lh32 - 16; ss1 = ss1 < 0 ? 0 : (ss1 > 16 ? 16 : ss1);
        cp16(base + AHI + dA0, sh + lh32,      (uint32_t)ss0);
        cp16(base + AHI + dA1, sh + lh32 + 16, (uint32_t)ss1);
        cp16(base + ALO + dA0, sl + lh32,      (uint32_t)ss0);
        cp16(base + ALO + dA1, sl + lh32 + 16, (uint32_t)ss1);
        const char* bsh = bhp + c * 64;
        cp16(base + BHI + dA0, bsh + lh32,      16u);
        cp16(base + BHI + dA1, bsh + lh32 + 16, 16u);
        const char* bsl = blp + c * 64;
        cp16(base + BLO + dA0, bsl + lh32,      16u);
        cp16(base + BLO + dA1, bsl + lh32 + 16, 16u);
    };

    float acc[2][8][4];
#pragma unroll
    for (int i = 0; i < 2; i++)
#pragma unroll
        for (int j = 0; j < 8; j++)
#pragma unroll
            for (int q = 0; q < 4; q++) acc[i][j][q] = 0.0f;

    const int fr = lid & 15;
    const uint32_t a_col = (uint32_t)((lid >> 4) * 16);
    uint32_t a_soff[2];
#pragma unroll
    for (int mi = 0; mi < 2; mi++)
        a_soff[mi] = (uint32_t)((wm * 32 + mi * 16 + fr) * 64) + a_col;
    const uint32_t b_base = (uint32_t)((wn * 64 + (lid & 7) + ((lid >> 4) & 1) * 8) * 64 +
                                       (((lid >> 3) & 1) * 16));

    load_chunk(0, 0);
    CP_COMMIT();

    for (int c = 0; c < NC; c++) {
        if (c + 1 < NC) { load_chunk(c + 1, (c + 1) & 1); CP_COMMIT(); CP_WAIT(1); }
        else           { CP_WAIT(0); }
        __syncthreads();
        uint32_t bufb = sb + (c & 1) * BUF;

#pragma unroll
        for (int kk = 0; kk < 2; kk++) {
            uint32_t ah[2][4], al[2][4];
#pragma unroll
            for (int mi = 0; mi < 2; mi++) {
                uint32_t so = sw64(a_soff[mi] + (uint32_t)(kk * 32));
                LDMATRIX_X4(ah[mi][0], ah[mi][1], ah[mi][2], ah[mi][3], bufb + AHI + so);
                LDMATRIX_X4(al[mi][0], al[mi][1], al[mi][2], al[mi][3], bufb + ALO + so);
            }
#pragma unroll
            for (int ni = 0; ni < 8; ni += 2) {
                uint32_t so = sw64(b_base + (uint32_t)(ni * 8 * 64) + (uint32_t)(kk * 32));
                uint32_t bh0, bh1, bh2, bh3;
                LDMATRIX_X4(bh0, bh1, bh2, bh3, bufb + BHI + so);
                uint32_t bl0, bl1, bl2, bl3;
                LDMATRIX_X4(bl0, bl1, bl2, bl3, bufb + BLO + so);
#pragma unroll
                for (int mi = 0; mi < 2; mi++) {
                    float* d = acc[mi][ni];
                    mma_fp16(d[0], d[1], d[2], d[3],
                             ah[mi][0], ah[mi][1], ah[mi][2], ah[mi][3], bh0, bh1);
                    mma_fp16(d[0], d[1], d[2], d[3],
                             al[mi][0], al[mi][1], al[mi][2], al[mi][3], bh0, bh1);
                    mma_fp16(d[0], d[1], d[2], d[3],
                             ah[mi][0], ah[mi][1], ah[mi][2], ah[mi][3], bl0, bl1);
                    float* e = acc[mi][ni + 1];
                    mma_fp16(e[0], e[1], e[2], e[3],
                             ah[mi][0], ah[mi][1], ah[mi][2], ah[mi][3], bh2, bh3);
                    mma_fp16(e[0], e[1], e[2], e[3],
                             al[mi][0], al[mi][1], al[mi][2], al[mi][3], bh2, bh3);
                    mma_fp16(e[0], e[1], e[2], e[3],
                             ah[mi][0], ah[mi][1], ah[mi][2], ah[mi][3], bl2, bl3);
                }
            }
        }
        __syncthreads();
    }

    // ---- epilogue ----
#pragma unroll
    for (int mi = 0; mi < 2; mi++) {
        int r0 = m0 + wm * 32 + mi * 16 + (lid >> 2);
        int r1o = r0 + 8;
        float cv0 = 0.f, cv1 = 0.f;
        if (EPI == 4) {
            if (r0 < M) cv0 = cntp[r0];
            if (r1o < M) cv1 = cntp[r1o];
        }
#pragma unroll
        for (int ni = 0; ni < 8; ni++) {
            int gc = n0 + wn * 64 + ni * 8 + (lid & 3) * 2;
            float b0 = __ldg(bias + gc), b1 = __ldg(bias + gc + 1);
            float* d = acc[mi][ni];
            if (EPI == 0) {
                if (r0 < M)
                    *reinterpret_cast<float2*>(outf + (size_t)r0 * 512 + gc) =
                        make_float2(d[0] + b0, d[1] + b1);
                if (r1o < M)
                    *reinterpret_cast<float2*>(outf + (size_t)r1o * 512 + gc) =
                        make_float2(d[2] + b0, d[3] + b1);
            } else if (EPI == 1) {
                if (r0 < M) {
                    float a = gelu_exact(d[0] + b0), b = gelu_exact(d[1] + b1);
                    *reinterpret_cast<uint32_t*>(out_hi + (size_t)r0 * 512 + gc) = pack_half(a, b);
                    *reinterpret_cast<uint32_t*>(out_lo + (size_t)r0 * 512 + gc) =
                        pack_half(a - hi_half(a), b - hi_half(b));
                }
                if (r1o < M) {
                    float a = gelu_exact(d[2] + b0), b = gelu_exact(d[3] + b1);
                    *reinterpret_cast<uint32_t*>(out_hi + (size_t)r1o * 512 + gc) = pack_half(a, b);
                    *reinterpret_cast<uint32_t*>(out_lo + (size_t)r1o * 512 + gc) =
                        pack_half(a - hi_half(a), b - hi_half(b));
                }
            } else {  // EPI == 4
                if (r0 < M) {
                    float a = d[0] + cv0 * b0, b = d[1] + cv0 * b1;
                    *reinterpret_cast<uint32_t*>(out_hi + (size_t)r0 * 512 + gc) = pack_half(a, b);
                    *reinterpret_cast<uint32_t*>(out_lo + (size_t)r0 * 512 + gc) =
                        pack_half(a - hi_half(a), b - hi_half(b));
                }
                if (r1o < M) {
                    float a = d[2] + cv1 * b0, b = d[3] + cv1 * b1;
                    *reinterpret_cast<uint32_t*>(out_hi + (size_t)r1o * 512 + gc) = pack_half(a, b);
                    *reinterpret_cast<uint32_t*>(out_lo + (size_t)r1o * 512 + gc) =
                        pack_half(a - hi_half(a), b - hi_half(b));
                }
            }
        }
    }
}

// ---------------- edge gather: agg[dst] += gelu(P[src] + e_new @ W1e) ----------------
// W1e = msg_w1 rows 512..527 ([16][512] fp32), cached in SMEM.
// 8 warps/block, 2 edges per warp-iteration, 8 iterations -> 128 edges per block.
__global__ __launch_bounds__(256) void edge_gather_kernel(
    const float* __restrict__ P, const float* __restrict__ e_new,
    const float* __restrict__ w1e,
    const int* __restrict__ src, const int* __restrict__ dst,
    float* __restrict__ agg)
{
    __shared__ __align__(16) float ws[16 * 512];
    const int tid = threadIdx.x;
    for (int i = tid * 4; i < 8192; i += 1024)
        *reinterpret_cast<float4*>(ws + i) = *reinterpret_cast<const float4*>(w1e + i);
    __syncthreads();

    const int wid = tid >> 5, lane = tid & 31;
    const int base = blockIdx.x * 128 + wid * 16;
#pragma unroll 1
    for (int it = 0; it < 8; it++) {
        int e0 = base + it * 2, e1 = e0 + 1;
        float myv = e_new[(size_t)((lane < 16) ? e0 : e1) * EDD + (lane & 15)];
        float ek0[16], ek1[16];
#pragma unroll
        for (int k = 0; k < 16; k++) {
            ek0[k] = __shfl_sync(0xffffffffu, myv, k);
            ek1[k] = __shfl_sync(0xffffffffu, myv, 16 + k);
        }
        const float* p0 = P + (size_t)src[e0] * HH;
        const float* p1 = P + (size_t)src[e1] * HH;
        float* g0 = agg + (size_t)dst[e0] * HH;
        float* g1 = agg + (size_t)dst[e1] * HH;
#pragma unroll
        for (int j = 0; j < 8; j++) {
            int col = lane * 2 + j * 64;
            float2 a0 = *reinterpret_cast<const float2*>(p0 + col);
            float2 a1 = *reinterpret_cast<const float2*>(p1 + col);
#pragma unroll
            for (int k = 0; k < 16; k++) {
                float2 w = *reinterpret_cast<const float2*>(ws + k * 512 + col);
                a0.x += ek0[k] * w.x; a0.y += ek0[k] * w.y;
                a1.x += ek1[k] * w.x; a1.y += ek1[k] * w.y;
            }
            a0.x = gelu_exact(a0.x); a0.y = gelu_exact(a0.y);
            a1.x = gelu_exact(a1.x); a1.y = gelu_exact(a1.y);
            asm volatile("red.global.add.v2.f32 [%0], {%1,%2};"
                         :: "l"(g0 + col), "f"(a0.x), "f"(a0.y) : "memory");
            asm volatile("red.global.add.v2.f32 [%0], {%1,%2};"
                         :: "l"(g1 + col), "f"(a1.x), "f"(a1.y) : "memory");
        }
    }
}

// ---------------- edge update: SMEM-cached weights, 2 edges per warp ----------------
__global__ __launch_bounds__(256) void edge_update_kernel(
    const float* __restrict__ h,
    const float* __restrict__ edge_attr,
    const float* __restrict__ em_w1, const float* __restrict__ em_b1,
    const float* __restrict__ em_w2, const float* __restrict__ em_b2,
    const float* __restrict__ eg_w,  const float* __restrict__ eg_b,
    const float* __restrict__ en_g,  const float* __restrict__ en_b,
    const int* __restrict__ src, const int* __restrict__ dst,
    float* __restrict__ e_new)
{
    extern __shared__ __align__(16) float wt[];   // 17 * 1040 floats
    const int tid = threadIdx.x;
    const int wid = tid >> 5, lane = tid & 31;

    for (int t = tid; t < 1040 * 16; t += 256) {
        int i = t >> 4, j = t & 15;
        wt[j * 1040 + i] = em_w1[t];
    }
    for (int t = tid; t < 1040; t += 256)
        wt[16 * 1040 + t] = eg_w[t];
    __syncthreads();

    const int half = lane >> 4;
    const int loc  = lane & 15;

    const int ctaBase = blockIdx.x * 128;
#pragma unroll 1
    for (int it = 0; it < 8; it++) {
        int e0 = ctaBase + wid * 16 + it * 2;
        int e1 = e0 + 1;
        const float* hs0 = h + (size_t)src[e0] * HH;
        const float* hd0 = h + (size_t)dst[e0] * HH;
        const float* hs1 = h + (size_t)src[e1] * HH;
        const float* hd1 = h + (size_t)dst[e1] * HH;

        float acc0[17], acc1[17];
#pragma unroll
        for (int j = 0; j < 17; j++) { acc0[j] = 0.0f; acc1[j] = 0.0f; }

#pragma unroll
        for (int blk = 0; blk < 8; blk++) {
            int i0 = blk * 128 + lane * 4;
            float4 z0 = (i0 < 512) ? *reinterpret_cast<const float4*>(hs0 + i0)
                                   : *reinterpret_cast<const float4*>(hd0 + i0 - 512);
            float4 z1 = (i0 < 512) ? *reinterpret_cast<const float4*>(hs1 + i0)
                                   : *reinterpret_cast<const float4*>(hd1 + i0 - 512);
#pragma unroll
            for (int j = 0; j < 17; j++) {
                float4 w = *reinterpret_cast<const float4*>(&wt[j * 1040 + i0]);
                acc0[j] += z0.x * w.x + z0.y * w.y + z0.z * w.z + z0.w * w.w;
                acc1[j] += z1.x * w.x + z1.y * w.y + z1.z * w.z + z1.w * w.w;
            }
        }
        if (lane < 4) {
            int i0 = 1024 + lane * 4;
            float4 z0 = *reinterpret_cast<const float4*>(edge_attr + (size_t)e0 * EDD + lane * 4);
            float4 z1 = *reinterpret_cast<const float4*>(edge_attr + (size_t)e1 * EDD + lane * 4);
#pragma unroll
            for (int j = 0; j < 17; j++) {
                float4 w = *reinterpret_cast<const float4*>(&wt[j * 1040 + i0]);
                acc0[j] += z0.x * w.x + z0.y * w.y + z0.z * w.z + z0.w * w.w;
                acc1[j] += z1.x * w.x + z1.y * w.y + z1.z * w.z + z1.w * w.w;
            }
        }

#pragma unroll
        for (int j = 0; j < 17; j++) {
#pragma unroll
            for (int o = 16; o > 0; o >>= 1) {
                acc0[j] += __shfl_xor_sync(0xffffffffu, acc0[j], o);
                acc1[j] += __shfl_xor_sync(0xffffffffu, acc1[j], o);
            }
        }

        int e = half ? e1 : e0;
        float a16 = half ? acc1[16] : acc0[16];
        float aj  = half ? acc1[loc] : acc0[loc];
        float gate = 1.0f / (1.0f + expf(-(a16 + eg_b[0])));
        float gv = gelu_exact(aj + em_b1[loc]);

        float delta = em_b2[loc];
#pragma unroll
        for (int k = 0; k < 16; k++) {
            float gk = __shfl_sync(0xffffffffu, gv, k + (half << 4));
            delta += gk * em_w2[k * 16 + loc];
        }

        float x = edge_attr[(size_t)e * EDD + loc] + EDGE_SCALE * gate * delta;

        float s = x;
#pragma unroll
        for (int o = 8; o > 0; o >>= 1) s += __shfl_xor_sync(0xffffffffu, s, o);
        float mu = s * (1.0f / 16.0f);
        float d = x - mu;
        float v = d * d;
#pragma unroll
        for (int o = 8; o > 0; o >>= 1) v += __shfl_xor_sync(0xffffffffu, v, o);
        float r = rsqrtf(v * (1.0f / 16.0f) + LNEPS);
        float val = d * r * en_g[loc] + en_b[loc];
        e_new[(size_t)e * EDD + loc] = val;
    }
}

// ---------------- residual + LayerNorm over 512 ----------------
__global__ __launch_bounds__(128) void node_out_kernel(
    const float* __restrict__ h, const float* __restrict__ h2,
    const float* __restrict__ g, const float* __restrict__ b,
    float* __restrict__ out)
{
    int n = blockIdx.x;
    int t = threadIdx.x;
    const float* hr  = h  + (size_t)n * HH;
    const float* h2r = h2 + (size_t)n * HH;

    float x[4];
    float s = 0.0f;
#pragma unroll
    for (int i = 0; i < 4; i++) {
        int c = t + 128 * i;
        x[i] = hr[c] + h2r[c];
        s += x[i];
    }
    __shared__ float red[4];
#pragma unroll
    for (int o = 16; o > 0; o >>= 1) s += __shfl_xor_sync(0xffffffffu, s, o);
    int warp = t >> 5, lane = t & 31;
    if (lane == 0) red[warp] = s;
    __syncthreads();
    float mu = (red[0] + red[1] + red[2] + red[3]) * (1.0f / 512.0f);

    float v = 0.0f;
#pragma unroll
    for (int i = 0; i < 4; i++) { float d = x[i] - mu; v += d * d; }
#pragma unroll
    for (int o = 16; o > 0; o >>= 1) v += __shfl_xor_sync(0xffffffffu, v, o);
    __syncthreads();
    if (lane == 0) red[warp] = v;
    __syncthreads();
    float var = (red[0] + red[1] + red[2] + red[3]) * (1.0f / 512.0f);
    float r = rsqrtf(var + LNEPS);

#pragma unroll
    for (int i = 0; i < 4; i++) {
        int c = t + 128 * i;
        out[(size_t)n * HH + c] = (x[i] - mu) * r * g[c] + b[c];
    }
}

// ---------------- launch ----------------
extern "C" void kernel_launch(void* const* d_in, const int* in_sizes, int n_in,
                              void* d_out, int out_size)
{
    const float* h       = (const float*)d_in[0];
    const float* edge_a  = (const float*)d_in[1];
    const float* msg_w1  = (const float*)d_in[2];
    const float* msg_b1  = (const float*)d_in[3];
    const float* msg_w2  = (const float*)d_in[4];
    const float* msg_b2  = (const float*)d_in[5];
    const float* upd_w1  = (const float*)d_in[6];
    const float* upd_b1  = (const float*)d_in[7];
    const float* upd_w2  = (const float*)d_in[8];
    const float* upd_b2  = (const float*)d_in[9];
    const float* norm_g  = (const float*)d_in[10];
    const float* norm_b  = (const float*)d_in[11];
    const float* em_w1   = (const float*)d_in[12];
    const float* em_b1   = (const float*)d_in[13];
    const float* em_w2   = (const float*)d_in[14];
    const float* em_b2   = (const float*)d_in[15];
    const float* eg_w    = (const float*)d_in[16];
    const float* eg_b    = (const float*)d_in[17];
    const float* en_g    = (const float*)d_in[18];
    const float* en_b    = (const float*)d_in[19];
    const int*   eindex  = (const int*)d_in[20];
    const int*   src = eindex;
    const int*   dst = eindex + EE;

    float* h_out = (float*)d_out;
    float* e_new = (float*)d_out + (size_t)NN * HH;

    __half *t1hi, *t1lo, *Uhi, *Ulo, *hhi, *hlo, *ahi, *alo;
    __half *w1hi, *w1lo, *w2hi, *w2lo, *u1hi, *u1lo, *u2hi, *u2lo;
    float *P, *agg, *h2, *cnt;
    cudaGetSymbolAddress((void**)&t1hi, g_t1hi); cudaGetSymbolAddress((void**)&t1lo, g_t1lo);
    cudaGetSymbolAddress((void**)&Uhi, g_Uhi);  cudaGetSymbolAddress((void**)&Ulo, g_Ulo);
    cudaGetSymbolAddress((void**)&agg, g_agg);  cudaGetSymbolAddress((void**)&h2,  g_h2);
    cudaGetSymbolAddress((void**)&hhi, g_hhi);  cudaGetSymbolAddress((void**)&hlo, g_hlo);
    cudaGetSymbolAddress((void**)&ahi, g_ahi);  cudaGetSymbolAddress((void**)&alo, g_alo);
    cudaGetSymbolAddress((void**)&P,   g_P);    cudaGetSymbolAddress((void**)&cnt, g_cnt);
    cudaGetSymbolAddress((void**)&w1hi, g_w1hi); cudaGetSymbolAddress((void**)&w1lo, g_w1lo);
    cudaGetSymbolAddress((void**)&w2hi, g_w2hi); cudaGetSymbolAddress((void**)&w2lo, g_w2lo);
    cudaGetSymbolAddress((void**)&u1hi, g_u1hi); cudaGetSymbolAddress((void**)&u1lo, g_u1lo);
    cudaGetSymbolAddress((void**)&u2hi, g_u2hi); cudaGetSymbolAddress((void**)&u2lo, g_u2lo);

    cudaFuncSetAttribute(mma_gemm<0>, cudaFuncAttributeMaxDynamicSharedMemorySize, 65536);
    cudaFuncSetAttribute(mma_gemm<1>, cudaFuncAttributeMaxDynamicSharedMemorySize, 65536);
    cudaFuncSetAttribute(mma_gemm<4>, cudaFuncAttributeMaxDynamicSharedMemorySize, 65536);
    cudaFuncSetAttribute(edge_update_kernel, cudaFuncAttributeMaxDynamicSharedMemorySize, 72000);

    // weight prep (msg_w1: only rows 0..511 go through the GEMM; rows 512..527 used raw)
    dim3 wb(32, 8);
    wsplit_kernel<<<dim3(512 / 32, 16), wb>>>(msg_w1, 512, 512, w1hi, w1lo);
    wsplit_kernel<<<dim3(512 / 32, 16), wb>>>(msg_w2, 512, 512, w2hi, w2lo);
    wsplit_kernel<<<dim3(1024 / 32, 16), wb>>>(upd_w1, 1024, 1024, u1hi, u1lo);
    wsplit_kernel<<<dim3(512 / 32, 16), wb>>>(upd_w2, 512, 512, u2hi, u2lo);

    // split h; zero agg + cnt; count edges per node
    fsplit_kernel<<<(NN * HH / 4 + 255) / 256, 256>>>((const float4*)h, (uint2*)hhi, (uint2*)hlo, NN * HH / 4);
    zero_kernel<<<(NN * HH / 4 + 255) / 256, 256>>>((float4*)agg, NN * HH / 4);
    zero_kernel<<<(NN / 4 + 255) / 256, 256>>>((float4*)cnt, NN / 4);
    count_kernel<<<(EE + 255) / 256, 256>>>(dst, cnt);

    // edge update -> e_new (d_out)
    edge_update_kernel<<<EE / 128, 256, 17 * 1040 * 4>>>(
        h, edge_a, em_w1, em_b1, em_w2, em_b2, eg_w, eg_b, en_g, en_b,
        src, dst, e_new);

    // P = h @ msg_w1[:512] + b1   (N x 512 x 512, 3-pass, fp32 out)
    mma_gemm<0><<<dim3(4, (NN + 127) / 128), 256, 65536>>>(
        hhi, hlo, HH, 16, hhi, hlo, HH, 0,
        w1hi, w1lo, 512, msg_b1, P, nullptr, nullptr, nullptr, NN);

    // agg[dst] += gelu(P[src] + e_new @ msg_w1[512:])   (elementwise + rank-16)
    edge_gather_kernel<<<EE / 128, 256>>>(P, e_new, msg_w1 + 512 * 512, src, dst, agg);

    // split agg
    fsplit_kernel<<<(NN * HH / 4 + 255) / 256, 256>>>((const float4*)agg, (uint2*)t1hi, (uint2*)t1lo, NN * HH / 4);

    // stage 4 (N-scale): msgagg = agg @ msg_w2 + cnt*b2  -> fp16 hi/lo
    mma_gemm<4><<<dim3(4, (NN + 127) / 128), 256, 65536>>>(
        t1hi, t1lo, HH, 16, t1hi, t1lo, HH, 0,
        w2hi, w2lo, 512, msg_b2, nullptr, ahi, alo, cnt, NN);

    // stage 5: U = gelu([h | msgagg] @ upd_w1 + b1)  (Kp=1024)
    mma_gemm<1><<<dim3(4, (NN + 127) / 128), 256, 65536>>>(
        hhi, hlo, HH, 16, ahi, alo, HH, 1024,
        u1hi, u1lo, 1024, upd_b1, nullptr, Uhi, Ulo, nullptr, NN);

    // stage 6: h2 = U @ upd_w2 + b2
    mma_gemm<0><<<dim3(4, (NN + 127) / 128), 256, 65536>>>(
        Uhi, Ulo, HH, 16, Uhi, Ulo, HH, 0,
        u2hi, u2lo, 512, upd_b2, h2, nullptr, nullptr, nullptr, NN);

    // h_out = LN(h + h2)
    node_out_kernel<<<NN, 128>>>(h, h2, norm_g, norm_b, h_out);
}

// round 16
// speedup vs baseline: 12.8707x; 4.6520x over previous
#include <cuda_runtime.h>
#include <cuda_fp16.h>
#include <math.h>
#include <stdint.h>

#define NN 10000
#define EE 160000
#define HH 512
#define EDD 16
#define LNEPS 1e-5f
#define EDGE_SCALE 0.1f

// ---------------- scratch (no allocations allowed) ----------------
__device__ float  g_P[(size_t)NN * HH];      // h @ msg_w1[:512] + b1
__device__ float  g_agg[(size_t)NN * HH];    // scatter-sum of gelu messages
__device__ __half g_t1hi[(size_t)NN * HH];   // agg hi/lo (stage-4 A)
__device__ __half g_t1lo[(size_t)NN * HH];
__device__ __half g_ahi[(size_t)NN * HH];    // msg output agg hi/lo (stage-5 A2)
__device__ __half g_alo[(size_t)NN * HH];
__device__ __half g_Uhi[(size_t)NN * HH];
__device__ __half g_Ulo[(size_t)NN * HH];
__device__ float  g_h2[(size_t)NN * HH];
__device__ __half g_hhi[(size_t)NN * HH];
__device__ __half g_hlo[(size_t)NN * HH];
__device__ float  g_cnt[NN];
__device__ float  g_Ps[(size_t)NN * 17];     // h @ em_w1[:512]|eg_w[:512]
__device__ float  g_Pd[(size_t)NN * 17];     // h @ em_w1[512:1024]|eg_w[512:1024]
// transposed + split weights: [512][Kp] fp16 (n-major, k contiguous)
__device__ __half g_w1hi[512 * 512],  g_w1lo[512 * 512];   // msg_w1 rows 0..511
__device__ __half g_w2hi[512 * 512];                       // msg_w2 (2-pass: hi only)
__device__ __half g_u1hi[512 * 1024];                      // upd_w1
__device__ __half g_u2hi[512 * 512];                       // upd_w2

__device__ __forceinline__ float gelu_exact(float x) {
    return 0.5f * x * (1.0f + erff(x * 0.70710678118654752440f));
}

__device__ __forceinline__ uint32_t smem_u32(const void* p) {
    uint32_t a;
    asm("{ .reg .u64 t; cvta.to.shared.u64 t, %1; cvt.u32.u64 %0, t; }" : "=r"(a) : "l"(p));
    return a;
}

__device__ __forceinline__ uint32_t sw64(uint32_t x) {
    return x ^ (((x >> 7) & 3u) << 4);
}

__device__ __forceinline__ uint32_t pack_half(float a, float b) {
    __half2 p = __floats2half2_rn(a, b);
    return *reinterpret_cast<uint32_t*>(&p);
}
__device__ __forceinline__ float hi_half(float x) {
    return __half2float(__float2half_rn(x));
}

#define LDMATRIX_X4(r0, r1, r2, r3, addr) \
    asm volatile("ldmatrix.sync.aligned.m8n8.x4.shared.b16 {%0,%1,%2,%3}, [%4];" \
                 : "=r"(r0), "=r"(r1), "=r"(r2), "=r"(r3) : "r"(addr))

__device__ __forceinline__ void mma_fp16(float& d0, float& d1, float& d2, float& d3,
                                         uint32_t a0, uint32_t a1, uint32_t a2, uint32_t a3,
                                         uint32_t b0, uint32_t b1) {
    asm volatile(
        "mma.sync.aligned.m16n8k16.row.col.f32.f16.f16.f32 "
        "{%0,%1,%2,%3}, {%4,%5,%6,%7}, {%8,%9}, {%0,%1,%2,%3};"
        : "+f"(d0), "+f"(d1), "+f"(d2), "+f"(d3)
        : "r"(a0), "r"(a1), "r"(a2), "r"(a3), "r"(b0), "r"(b1));
}

__device__ __forceinline__ void cp16(uint32_t dst, const void* src, uint32_t ss) {
    asm volatile("cp.async.cg.shared.global [%0], [%1], 16, %2;"
                 :: "r"(dst), "l"(src), "r"(ss) : "memory");
}
#define CP_COMMIT() asm volatile("cp.async.commit_group;" ::: "memory")
#define CP_WAIT(n)  asm volatile("cp.async.wait_group %0;" :: "n"(n) : "memory")

// ---------------- weight transpose + fp16 hi/lo split ----------------
__global__ void wsplit_kernel(const float* __restrict__ W, int K, int Kp,
                              __half* __restrict__ ohi, __half* __restrict__ olo) {
    __shared__ float t[32][33];
    int kb = blockIdx.x * 32, nb = blockIdx.y * 32;
    int tx = threadIdx.x, ty = threadIdx.y;  // 32 x 8
#pragma unroll
    for (int r = 0; r < 4; r++) {
        int k = kb + ty + r * 8;
        t[ty + r * 8][tx] = (k < K) ? W[(size_t)k * 512 + nb + tx] : 0.0f;
    }
    __syncthreads();
#pragma unroll
    for (int r = 0; r < 4; r++) {
        int n = nb + ty + r * 8;
        int k = kb + tx;
        float v = t[tx][ty + r * 8];
        __half h = __float2half_rn(v);
        ohi[(size_t)n * Kp + k] = h;
        if (olo) olo[(size_t)n * Kp + k] = __float2half_rn(v - __half2float(h));
    }
}

// ---------------- fp32 -> fp16 hi/lo elementwise split ----------------
__global__ void fsplit_kernel(const float4* __restrict__ in,
                              uint2* __restrict__ oh, uint2* __restrict__ ol, int n4) {
    int i = blockIdx.x * blockDim.x + threadIdx.x;
    if (i >= n4) return;
    float4 f = in[i];
    oh[i] = make_uint2(pack_half(f.x, f.y), pack_half(f.z, f.w));
    ol[i] = make_uint2(pack_half(f.x - hi_half(f.x), f.y - hi_half(f.y)),
                       pack_half(f.z - hi_half(f.z), f.w - hi_half(f.w)));
}

// ---------------- zero ----------------
__global__ void zero_kernel(float4* __restrict__ p, int n4) {
    int i = blockIdx.x * blockDim.x + threadIdx.x;
    if (i < n4) p[i] = make_float4(0.f, 0.f, 0.f, 0.f);
}

// ---------------- edge-count histogram ----------------
__global__ void count_kernel(const int* __restrict__ dst, float* __restrict__ cnt) {
    int e = blockIdx.x * blockDim.x + threadIdx.x;
    if (e < EE) atomicAdd(&cnt[dst[e]], 1.0f);
}

// ---------------- Ps/Pd: h @ (em_w1 halves | eg_w halves) -> N x 17 each ----------------
__global__ __launch_bounds__(256) void psd_kernel(
    const float* __restrict__ h,
    const float* __restrict__ em_w1, const float* __restrict__ eg_w,
    float* __restrict__ Ps, float* __restrict__ Pd)
{
    extern __shared__ __align__(16) float ws[];   // [17][512] src + [17][512] dst
    float* wd = ws + 17 * 512;
    const int tid = threadIdx.x;
    for (int t = tid; t < 512 * 16; t += 256) {
        int k = t >> 4, j = t & 15;
        ws[j * 512 + k] = em_w1[t];
        wd[j * 512 + k] = em_w1[512 * 16 + t];
    }
    for (int t = tid; t < 512; t += 256) {
        ws[16 * 512 + t] = eg_w[t];
        wd[16 * 512 + t] = eg_w[512 + t];
    }
    __syncthreads();

    const int wid = tid >> 5, lane = tid & 31;
    int node = blockIdx.x * 8 + wid;
    if (node >= NN) return;
    const float* hr = h + (size_t)node * HH;

    float acc[34];
#pragma unroll
    for (int j = 0; j < 34; j++) acc[j] = 0.0f;

#pragma unroll
    for (int blk = 0; blk < 4; blk++) {
        int i0 = blk * 128 + lane * 4;
        float4 z = *reinterpret_cast<const float4*>(hr + i0);
#pragma unroll
        for (int j = 0; j < 17; j++) {
            float4 w = *reinterpret_cast<const float4*>(&ws[j * 512 + i0]);
            acc[j] += z.x * w.x + z.y * w.y + z.z * w.z + z.w * w.w;
            float4 v = *reinterpret_cast<const float4*>(&wd[j * 512 + i0]);
            acc[17 + j] += z.x * v.x + z.y * v.y + z.z * v.z + z.w * v.w;
        }
    }
#pragma unroll
    for (int j = 0; j < 34; j++) {
#pragma unroll
        for (int o = 16; o > 0; o >>= 1)
            acc[j] += __shfl_xor_sync(0xffffffffu, acc[j], o);
    }
    if (lane < 17) {
        float v0 = 0.f, v1 = 0.f;
#pragma unroll
        for (int j = 0; j < 17; j++)
            if (lane == j) { v0 = acc[j]; v1 = acc[17 + j]; }
        Ps[(size_t)node * 17 + lane] = v0;
        Pd[(size_t)node * 17 + lane] = v1;
    }
}

// ---------------- edge update (lite): gate + rank-16 MLP + LN ----------------
__global__ __launch_bounds__(256) void edge_lite_kernel(
    const float* __restrict__ Ps, const float* __restrict__ Pd,
    const float* __restrict__ edge_attr,
    const float* __restrict__ w1e,   // em_w1 + 1024*16: [16][16]
    const float* __restrict__ em_b1, const float* __restrict__ em_w2,
    const float* __restrict__ em_b2,
    const float* __restrict__ eg_we, // eg_w + 1024: [16]
    const float* __restrict__ eg_b,
    const float* __restrict__ en_g,  const float* __restrict__ en_b,
    const int* __restrict__ src, const int* __restrict__ dst,
    float* __restrict__ e_new)
{
    __shared__ float w1s[256], w2s[256], eges[16];
    const int tid = threadIdx.x;
    if (tid < 256) { w1s[tid] = w1e[tid]; w2s[tid] = em_w2[tid]; }
    if (tid < 16) eges[tid] = eg_we[tid];
    __syncthreads();

    const int wid = tid >> 5, lane = tid & 31;
    const int half = lane >> 4, loc = lane & 15;
    const int base = blockIdx.x * 128 + wid * 16;

#pragma unroll 1
    for (int it = 0; it < 8; it++) {
        int e = base + it * 2 + half;
        int s = src[e], d = dst[e];
        float myea = edge_attr[(size_t)e * EDD + loc];

        float accj = Ps[(size_t)s * 17 + loc] + Pd[(size_t)d * 17 + loc];
        float g = Ps[(size_t)s * 17 + 16] + Pd[(size_t)d * 17 + 16];

#pragma unroll
        for (int k = 0; k < 16; k++) {
            float eak = __shfl_sync(0xffffffffu, myea, k + (half << 4));
            accj += eak * w1s[k * 16 + loc];
            g += eak * eges[k];
        }
        float gate = 1.0f / (1.0f + expf(-(g + eg_b[0])));
        float gv = gelu_exact(accj + em_b1[loc]);

        float delta = em_b2[loc];
#pragma unroll
        for (int k = 0; k < 16; k++) {
            float gk = __shfl_sync(0xffffffffu, gv, k + (half << 4));
            delta += gk * w2s[k * 16 + loc];
        }

        float x = myea + EDGE_SCALE * gate * delta;
        float sred = x;
#pragma unroll
        for (int o = 8; o > 0; o >>= 1) sred += __shfl_xor_sync(0xffffffffu, sred, o);
        float mu = sred * (1.0f / 16.0f);
        float dd = x - mu;
        float v = dd * dd;
#pragma unroll
        for (int o = 8; o > 0; o >>= 1) v += __shfl_xor_sync(0xffffffffu, v, o);
        float r = rsqrtf(v * (1.0f / 16.0f) + LNEPS);
        e_new[(size_t)e * EDD + loc] = dd * r * en_g[loc] + en_b[loc];
    }
}

// ---------------- HMMA GEMM, cp.async double-buffered, fp16 multi-pass ----------------
// PASSES 2: D = Ah*Bh + Al*Bh (err ~2^-12);  PASSES 3: += Ah*Bl (err ~2^-22)
// EPI 0: fp32 store (+bias); EPI 1: gelu -> fp16 hi/lo (+bias); EPI 4: acc + cnt*bias -> fp16 hi/lo
template <int PASSES, int EPI>
__global__ __launch_bounds__(256) void mma_gemm(
    const __half* __restrict__ a1h, const __half* __restrict__ a1l,
    int s1, int C1,
    const __half* __restrict__ a2h, const __half* __restrict__ a2l,
    int s2, int tb2,
    const __half* __restrict__ bh, const __half* __restrict__ bl, int Kp,
    const float* __restrict__ bias,
    float* __restrict__ outf,
    __half* __restrict__ out_hi, __half* __restrict__ out_lo,
    const float* __restrict__ cntp, int M)
{
    extern __shared__ __align__(16) char smem[];
    constexpr int AHI = 0, ALO = 8192, BHI = 16384, BLO = 24576;
    constexpr int BUF = (PASSES == 3) ? 32768 : 24576;

    const int tid = threadIdx.x;
    const int wid = tid >> 5, lid = tid & 31;
    const int m0 = blockIdx.y * 128;
    const int n0 = blockIdx.x * 128;
    const int wm = wid & 3;
    const int wn = wid >> 2;
    const int NC = Kp / 32;
    const uint32_t sb = smem_u32(smem);

    const int lrow = tid >> 1;
    const int lh32 = (tid & 1) * 32;
    const int grA = m0 + lrow;
    const bool rowok = (grA < M);
    const char* a1hp = (const char*)(a1h + (size_t)(rowok ? grA : 0) * s1);
    const char* a1lp = (const char*)(a1l + (size_t)(rowok ? grA : 0) * s1);
    const char* a2hp = (const char*)(a2h + (size_t)(rowok ? grA : 0) * s2);
    const char* a2lp = (const char*)(a2l + (size_t)(rowok ? grA : 0) * s2);
    const char* bhp = (const char*)(bh + (size_t)(n0 + lrow) * Kp);
    const char* blp = (const char*)(bl + (size_t)(n0 + lrow) * Kp);

    const uint32_t dA0 = sw64((uint32_t)(lrow * 64 + lh32));
    const uint32_t dA1 = sw64((uint32_t)(lrow * 64 + lh32 + 16));

    auto load_chunk = [&](int c, int bufi) {
        uint32_t base = sb + bufi * BUF;
        const char *sh, *sl;
        int valid;
        if (c < C1) {
            sh = a1hp + c * 64; sl = a1lp + c * 64;
            valid = rowok ? 64 : 0;
        } else {
            int off = (c - C1) * 64;
            sh = a2hp + off; sl = a2lp + off;
            int v = tb2 - off;
            v = v < 0 ? 0 : (v > 64 ? 64 : v);
            valid = rowok ? v : 0;
        }
        int ss0 = valid - lh32;      ss0 = ss0 < 0 ? 0 : (ss0 > 16 ? 16 : ss0);
        int ss1 = valid - lh32 - 16; ss1 = ss1 < 0 ? 0 : (ss1 > 16 ? 16 : ss1);
        cp16(base + AHI + dA0, sh + lh32,      (uint32_t)ss0);
        cp16(base + AHI + dA1, sh + lh32 + 16, (uint32_t)ss1);
        cp16(base + ALO + dA0, sl + lh32,      (uint32_t)ss0);
        cp16(base + ALO + dA1, sl + lh32 + 16, (uint32_t)ss1);
        const char* bsh = bhp + c * 64;
        cp16(base + BHI + dA0, bsh + lh32,      16u);
        cp16(base + BHI + dA1, bsh + lh32 + 16, 16u);
        if (PASSES == 3) {
            const char* bsl = blp + c * 64;
            cp16(base + BLO + dA0, bsl + lh32,      16u);
            cp16(base + BLO + dA1, bsl + lh32 + 16, 16u);
        }
    };

    float acc[2][8][4];
#pragma unroll
    for (int i = 0; i < 2; i++)
#pragma unroll
        for (int j = 0; j < 8; j++)
#pragma unroll
            for (int q = 0; q < 4; q++) acc[i][j][q] = 0.0f;

    const int fr = lid & 15;
    const uint32_t a_col = (uint32_t)((lid >> 4) * 16);
    uint32_t a_soff[2];
#pragma unroll
    for (int mi = 0; mi < 2; mi++)
        a_soff[mi] = (uint32_t)((wm * 32 + mi * 16 + fr) * 64) + a_col;
    const uint32_t b_base = (uint32_t)((wn * 64 + (lid & 7) + ((lid >> 4) & 1) * 8) * 64 +
                                       (((lid >> 3) & 1) * 16));

    load_chunk(0, 0);
    CP_COMMIT();

    for (int c = 0; c < NC; c++) {
        if (c + 1 < NC) { load_chunk(c + 1, (c + 1) & 1); CP_COMMIT(); CP_WAIT(1); }
        else           { CP_WAIT(0); }
        __syncthreads();
        uint32_t bufb = sb + (c & 1) * BUF;

#pragma unroll
        for (int kk = 0; kk < 2; kk++) {
            uint32_t ah[2][4], al[2][4];
#pragma unroll
            for (int mi = 0; mi < 2; mi++) {
                uint32_t so = sw64(a_soff[mi] + (uint32_t)(kk * 32));
                LDMATRIX_X4(ah[mi][0], ah[mi][1], ah[mi][2], ah[mi][3], bufb + AHI + so);
                LDMATRIX_X4(al[mi][0], al[mi][1], al[mi][2], al[mi][3], bufb + ALO + so);
            }
#pragma unroll
            for (int ni = 0; ni < 8; ni += 2) {
                uint32_t so = sw64(b_base + (uint32_t)(ni * 8 * 64) + (uint32_t)(kk * 32));
                uint32_t bh0, bh1, bh2, bh3;
                LDMATRIX_X4(bh0, bh1, bh2, bh3, bufb + BHI + so);
                uint32_t bl0, bl1, bl2, bl3;
                if (PASSES == 3) LDMATRIX_X4(bl0, bl1, bl2, bl3, bufb + BLO + so);
#pragma unroll
                for (int mi = 0; mi < 2; mi++) {
                    float* d = acc[mi][ni];
                    mma_fp16(d[0], d[1], d[2], d[3],
                             ah[mi][0], ah[mi][1], ah[mi][2], ah[mi][3], bh0, bh1);
                    mma_fp16(d[0], d[1], d[2], d[3],
                             al[mi][0], al[mi][1], al[mi][2], al[mi][3], bh0, bh1);
                    if (PASSES == 3)
                        mma_fp16(d[0], d[1], d[2], d[3],
                                 ah[mi][0], ah[mi][1], ah[mi][2], ah[mi][3], bl0, bl1);
                    float* e = acc[mi][ni + 1];
                    mma_fp16(e[0], e[1], e[2], e[3],
                             ah[mi][0], ah[mi][1], ah[mi][2], ah[mi][3], bh2, bh3);
                    mma_fp16(e[0], e[1], e[2], e[3],
                             al[mi][0], al[mi][1], al[mi][2], al[mi][3], bh2, bh3);
                    if (PASSES == 3)
                        mma_fp16(e[0], e[1], e[2], e[3],
                                 ah[mi][0], ah[mi][1], ah[mi][2], ah[mi][3], bl2, bl3);
                }
            }
        }
        __syncthreads();
    }

    // ---- epilogue ----
#pragma unroll
    for (int mi = 0; mi < 2; mi++) {
        int r0 = m0 + wm * 32 + mi * 16 + (lid >> 2);
        int r1o = r0 + 8;
        float cv0 = 0.f, cv1 = 0.f;
        if (EPI == 4) {
            if (r0 < M) cv0 = cntp[r0];
            if (r1o < M) cv1 = cntp[r1o];
        }
#pragma unroll
        for (int ni = 0; ni < 8; ni++) {
            int gc = n0 + wn * 64 + ni * 8 + (lid & 3) * 2;
            float b0 = __ldg(bias + gc), b1 = __ldg(bias + gc + 1);
            float* d = acc[mi][ni];
            if (EPI == 0) {
                if (r0 < M)
                    *reinterpret_cast<float2*>(outf + (size_t)r0 * 512 + gc) =
                        make_float2(d[0] + b0, d[1] + b1);
                if (r1o < M)
                    *reinterpret_cast<float2*>(outf + (size_t)r1o * 512 + gc) =
                        make_float2(d[2] + b0, d[3] + b1);
            } else if (EPI == 1) {
                if (r0 < M) {
                    float a = gelu_exact(d[0] + b0), b = gelu_exact(d[1] + b1);
                    *reinterpret_cast<uint32_t*>(out_hi + (size_t)r0 * 512 + gc) = pack_half(a, b);
                    *reinterpret_cast<uint32_t*>(out_lo + (size_t)r0 * 512 + gc) =
                        pack_half(a - hi_half(a), b - hi_half(b));
                }
                if (r1o < M) {
                    float a = gelu_exact(d[2] + b0), b = gelu_exact(d[3] + b1);
                    *reinterpret_cast<uint32_t*>(out_hi + (size_t)r1o * 512 + gc) = pack_half(a, b);
                    *reinterpret_cast<uint32_t*>(out_lo + (size_t)r1o * 512 + gc) =
                        pack_half(a - hi_half(a), b - hi_half(b));
                }
            } else {  // EPI == 4
                if (r0 < M) {
                    float a = d[0] + cv0 * b0, b = d[1] + cv0 * b1;
                    *reinterpret_cast<uint32_t*>(out_hi + (size_t)r0 * 512 + gc) = pack_half(a, b);
                    *reinterpret_cast<uint32_t*>(out_lo + (size_t)r0 * 512 + gc) =
                        pack_half(a - hi_half(a), b - hi_half(b));
                }
                if (r1o < M) {
                    float a = d[2] + cv1 * b0, b = d[3] + cv1 * b1;
                    *reinterpret_cast<uint32_t*>(out_hi + (size_t)r1o * 512 + gc) = pack_half(a, b);
                    *reinterpret_cast<uint32_t*>(out_lo + (size_t)r1o * 512 + gc) =
                        pack_half(a - hi_half(a), b - hi_half(b));
                }
            }
        }
    }
}

// ---------------- edge gather: agg[dst] += gelu(P[src] + e_new @ W1e) ----------------
__global__ __launch_bounds__(256) void edge_gather_kernel(
    const float* __restrict__ P, const float* __restrict__ e_new,
    const float* __restrict__ w1e,
    const int* __restrict__ src, const int* __restrict__ dst,
    float* __restrict__ agg)
{
    __shared__ __align__(16) float ws[16 * 512];
    const int tid = threadIdx.x;
    for (int i = tid * 4; i < 8192; i += 1024)
        *reinterpret_cast<float4*>(ws + i) = *reinterpret_cast<const float4*>(w1e + i);
    __syncthreads();

    const int wid = tid >> 5, lane = tid & 31;
    const int base = blockIdx.x * 128 + wid * 16;
#pragma unroll 1
    for (int it = 0; it < 8; it++) {
        int e0 = base + it * 2, e1 = e0 + 1;
        float myv = e_new[(size_t)((lane < 16) ? e0 : e1) * EDD + (lane & 15)];
        float ek0[16], ek1[16];
#pragma unroll
        for (int k = 0; k < 16; k++) {
            ek0[k] = __shfl_sync(0xffffffffu, myv, k);
            ek1[k] = __shfl_sync(0xffffffffu, myv, 16 + k);
        }
        const float* p0 = P + (size_t)src[e0] * HH;
        const float* p1 = P + (size_t)src[e1] * HH;
        float* g0 = agg + (size_t)dst[e0] * HH;
        float* g1 = agg + (size_t)dst[e1] * HH;
#pragma unroll
        for (int j = 0; j < 8; j++) {
            int col = lane * 2 + j * 64;
            float2 a0 = *reinterpret_cast<const float2*>(p0 + col);
            float2 a1 = *reinterpret_cast<const float2*>(p1 + col);
#pragma unroll
            for (int k = 0; k < 16; k++) {
                float2 w = *reinterpret_cast<const float2*>(ws + k * 512 + col);
                a0.x += ek0[k] * w.x; a0.y += ek0[k] * w.y;
                a1.x += ek1[k] * w.x; a1.y += ek1[k] * w.y;
            }
            a0.x = gelu_exact(a0.x); a0.y = gelu_exact(a0.y);
            a1.x = gelu_exact(a1.x); a1.y = gelu_exact(a1.y);
            asm volatile("red.global.add.v2.f32 [%0], {%1,%2};"
                         :: "l"(g0 + col), "f"(a0.x), "f"(a0.y) : "memory");
            asm volatile("red.global.add.v2.f32 [%0], {%1,%2};"
                         :: "l"(g1 + col), "f"(a1.x), "f"(a1.y) : "memory");
        }
    }
}

// ---------------- residual + LayerNorm over 512 ----------------
__global__ __launch_bounds__(128) void node_out_kernel(
    const float* __restrict__ h, const float* __restrict__ h2,
    const float* __restrict__ g, const float* __restrict__ b,
    float* __restrict__ out)
{
    int n = blockIdx.x;
    int t = threadIdx.x;
    const float* hr  = h  + (size_t)n * HH;
    const float* h2r = h2 + (size_t)n * HH;

    float x[4];
    float s = 0.0f;
#pragma unroll
    for (int i = 0; i < 4; i++) {
        int c = t + 128 * i;
        x[i] = hr[c] + h2r[c];
        s += x[i];
    }
    __shared__ float red[4];
#pragma unroll
    for (int o = 16; o > 0; o >>= 1) s += __shfl_xor_sync(0xffffffffu, s, o);
    int warp = t >> 5, lane = t & 31;
    if (lane == 0) red[warp] = s;
    __syncthreads();
    float mu = (red[0] + red[1] + red[2] + red[3]) * (1.0f / 512.0f);

    float v = 0.0f;
#pragma unroll
    for (int i = 0; i < 4; i++) { float d = x[i] - mu; v += d * d; }
#pragma unroll
    for (int o = 16; o > 0; o >>= 1) v += __shfl_xor_sync(0xffffffffu, v, o);
    __syncthreads();
    if (lane == 0) red[warp] = v;
    __syncthreads();
    float var = (red[0] + red[1] + red[2] + red[3]) * (1.0f / 512.0f);
    float r = rsqrtf(var + LNEPS);

#pragma unroll
    for (int i = 0; i < 4; i++) {
        int c = t + 128 * i;
        out[(size_t)n * HH + c] = (x[i] - mu) * r * g[c] + b[c];
    }
}

// ---------------- launch ----------------
extern "C" void kernel_launch(void* const* d_in, const int* in_sizes, int n_in,
                              void* d_out, int out_size)
{
    const float* h       = (const float*)d_in[0];
    const float* edge_a  = (const float*)d_in[1];
    const float* msg_w1  = (const float*)d_in[2];
    const float* msg_b1  = (const float*)d_in[3];
    const float* msg_w2  = (const float*)d_in[4];
    const float* msg_b2  = (const float*)d_in[5];
    const float* upd_w1  = (const float*)d_in[6];
    const float* upd_b1  = (const float*)d_in[7];
    const float* upd_w2  = (const float*)d_in[8];
    const float* upd_b2  = (const float*)d_in[9];
    const float* norm_g  = (const float*)d_in[10];
    const float* norm_b  = (const float*)d_in[11];
    const float* em_w1   = (const float*)d_in[12];
    const float* em_b1   = (const float*)d_in[13];
    const float* em_w2   = (const float*)d_in[14];
    const float* em_b2   = (const float*)d_in[15];
    const float* eg_w    = (const float*)d_in[16];
    const float* eg_b    = (const float*)d_in[17];
    const float* en_g    = (const float*)d_in[18];
    const float* en_b    = (const float*)d_in[19];
    const int*   eindex  = (const int*)d_in[20];
    const int*   src = eindex;
    const int*   dst = eindex + EE;

    float* h_out = (float*)d_out;
    float* e_new = (float*)d_out + (size_t)NN * HH;

    __half *t1hi, *t1lo, *Uhi, *Ulo, *hhi, *hlo, *ahi, *alo;
    __half *w1hi, *w1lo, *w2hi, *u1hi, *u2hi;
    float *P, *agg, *h2, *cnt, *Ps, *Pd;
    cudaGetSymbolAddress((void**)&t1hi, g_t1hi); cudaGetSymbolAddress((void**)&t1lo, g_t1lo);
    cudaGetSymbolAddress((void**)&Uhi, g_Uhi);  cudaGetSymbolAddress((void**)&Ulo, g_Ulo);
    cudaGetSymbolAddress((void**)&agg, g_agg);  cudaGetSymbolAddress((void**)&h2,  g_h2);
    cudaGetSymbolAddress((void**)&hhi, g_hhi);  cudaGetSymbolAddress((void**)&hlo, g_hlo);
    cudaGetSymbolAddress((void**)&ahi, g_ahi);  cudaGetSymbolAddress((void**)&alo, g_alo);
    cudaGetSymbolAddress((void**)&P,   g_P);    cudaGetSymbolAddress((void**)&cnt, g_cnt);
    cudaGetSymbolAddress((void**)&Ps,  g_Ps);   cudaGetSymbolAddress((void**)&Pd,  g_Pd);
    cudaGetSymbolAddress((void**)&w1hi, g_w1hi); cudaGetSymbolAddress((void**)&w1lo, g_w1lo);
    cudaGetSymbolAddress((void**)&w2hi, g_w2hi);
    cudaGetSymbolAddress((void**)&u1hi, g_u1hi);
    cudaGetSymbolAddress((void**)&u2hi, g_u2hi);

    cudaFuncSetAttribute(mma_gemm<3, 0>, cudaFuncAttributeMaxDynamicSharedMemorySize, 65536);
    cudaFuncSetAttribute(mma_gemm<2, 4>, cudaFuncAttributeMaxDynamicSharedMemorySize, 49152);
    cudaFuncSetAttribute(mma_gemm<2, 1>, cudaFuncAttributeMaxDynamicSharedMemorySize, 49152);
    cudaFuncSetAttribute(mma_gemm<2, 0>, cudaFuncAttributeMaxDynamicSharedMemorySize, 49152);
    cudaFuncSetAttribute(psd_kernel, cudaFuncAttributeMaxDynamicSharedMemorySize, 72000);

    // weight prep
    dim3 wb(32, 8);
    wsplit_kernel<<<dim3(512 / 32, 16), wb>>>(msg_w1, 512, 512, w1hi, w1lo);
    wsplit_kernel<<<dim3(512 / 32, 16), wb>>>(msg_w2, 512, 512, w2hi, nullptr);
    wsplit_kernel<<<dim3(1024 / 32, 16), wb>>>(upd_w1, 1024, 1024, u1hi, nullptr);
    wsplit_kernel<<<dim3(512 / 32, 16), wb>>>(upd_w2, 512, 512, u2hi, nullptr);

    // split h; zero agg + cnt; count edges per node
    fsplit_kernel<<<(NN * HH / 4 + 255) / 256, 256>>>((const float4*)h, (uint2*)hhi, (uint2*)hlo, NN * HH / 4);
    zero_kernel<<<(NN * HH / 4 + 255) / 256, 256>>>((float4*)agg, NN * HH / 4);
    zero_kernel<<<(NN / 4 + 255) / 256, 256>>>((float4*)cnt, NN / 4);
    count_kernel<<<(EE + 255) / 256, 256>>>(dst, cnt);

    // Ps/Pd (N x 17 each)
    psd_kernel<<<(NN + 7) / 8, 256, 2 * 17 * 512 * 4>>>(h, em_w1, eg_w, Ps, Pd);

    // edge update -> e_new (d_out)
    edge_lite_kernel<<<EE / 128, 256>>>(
        Ps, Pd, edge_a, em_w1 + 1024 * 16, em_b1, em_w2, em_b2,
        eg_w + 1024, eg_b, en_g, en_b, src, dst, e_new);

    // P = h @ msg_w1[:512] + b1   (3-pass, fp32 out)
    mma_gemm<3, 0><<<dim3(4, (NN + 127) / 128), 256, 65536>>>(
        hhi, hlo, HH, 16, hhi, hlo, HH, 0,
        w1hi, w1lo, 512, msg_b1, P, nullptr, nullptr, nullptr, NN);

    // agg[dst] += gelu(P[src] + e_new @ msg_w1[512:])
    edge_gather_kernel<<<EE / 128, 256>>>(P, e_new, msg_w1 + 512 * 512, src, dst, agg);

    // split agg
    fsplit_kernel<<<(NN * HH / 4 + 255) / 256, 256>>>((const float4*)agg, (uint2*)t1hi, (uint2*)t1lo, NN * HH / 4);

    // stage 4 (2-pass): msgagg = agg @ msg_w2 + cnt*b2  -> fp16 hi/lo
    mma_gemm<2, 4><<<dim3(4, (NN + 127) / 128), 256, 49152>>>(
        t1hi, t1lo, HH, 16, t1hi, t1lo, HH, 0,
        w2hi, nullptr, 512, msg_b2, nullptr, ahi, alo, cnt, NN);

    // stage 5 (2-pass): U = gelu([h | msgagg] @ upd_w1 + b1)  (Kp=1024)
    mma_gemm<2, 1><<<dim3(4, (NN + 127) / 128), 256, 49152>>>(
        hhi, hlo, HH, 16, ahi, alo, HH, 1024,
        u1hi, nullptr, 1024, upd_b1, nullptr, Uhi, Ulo, nullptr, NN);

    // stage 6 (2-pass): h2 = U @ upd_w2 + b2
    mma_gemm<2, 0><<<dim3(4, (NN + 127) / 128), 256, 49152>>>(
        Uhi, Ulo, HH, 16, Uhi, Ulo, HH, 0,
        u2hi, nullptr, 512, upd_b2, h2, nullptr, nullptr, nullptr, NN);

    // h_out = LN(h + h2)
    node_out_kernel<<<NN, 128>>>(h, h2, norm_g, norm_b, h_out);
}